// round 1
// baseline (speedup 1.0000x reference)
#include <cuda_runtime.h>
#include <math.h>

#define BB 8
#define CC 48
#define PP (BB*CC)          // 384 planes
#define N1 256
#define O1 133
#define N2 133
#define O2 72
#define N3 72
#define O3 41
#define HW (N1*N1)          // 65536
#define PIX3 (O3*O3)        // 1681
#define B3SZ (PP*PIX3)      // 645504
#define WBAND (CC*CC*PIX3)  // 3875904

__constant__ float DLO[12] = {
    -0.00107730108499558f, 0.004777257511010651f, 0.0005538422009938016f,
    -0.031582039318031156f, 0.02752286553001629f, 0.09750160558707936f,
    -0.12976686756709563f, -0.22626469396516913f, 0.3152503517092432f,
    0.7511339080215775f, 0.4946238903983854f, 0.11154074335008017f };
__constant__ float DHI[12] = {
    -0.11154074335008017f, 0.4946238903983854f, -0.7511339080215775f,
    0.3152503517092432f, 0.22626469396516913f, -0.12976686756709563f,
    -0.09750160558707936f, 0.02752286553001629f, 0.031582039318031156f,
    0.0005538422009938016f, -0.004777257511010651f, -0.00107730108499558f };

// ------------------- scratch arena (static device memory) -------------------
__device__ float g_h  [PP*HW];
__device__ float g_h1 [PP*HW];      // also holds 134x134 IDWT intermediate
__device__ float g_lo [PP*N1*O1];   // generic row/col scratch (max 256x133)
__device__ float g_hi [PP*N1*O1];
__device__ float g_ll1[PP*O1*O1];
__device__ float g_lh1[PP*O1*O1];
__device__ float g_hl1[PP*O1*O1];
__device__ float g_hh1[PP*O1*O1];
__device__ float g_ll2[PP*O2*O2];
__device__ float g_lh2[PP*O2*O2];
__device__ float g_hl2[PP*O2*O2];
__device__ float g_hh2[PP*O2*O2];
__device__ float g_b3 [8*B3SZ];     // slots: 0..3 raw ll,lh,hl,hh ; 4..7 mixed

__device__ __forceinline__ int symref(int i, int n) {
    int p = 2 * n;
    int m = i % p;
    if (m < 0) m += p;
    return (m < n) ? m : (p - 1 - m);
}

__device__ __forceinline__ float gelu_f(float x) {
    return 0.5f * x * (1.0f + erff(x * 0.7071067811865475f));
}

// ------------------------------ fc0 + pad -----------------------------------
__global__ void fc0_kernel(const float* __restrict__ x,
                           const float* __restrict__ w,
                           const float* __restrict__ b,
                           float* __restrict__ out) {
    int idx = blockIdx.x * blockDim.x + threadIdx.x;
    if (idx >= PP * HW) return;
    int p  = idx & (HW - 1);
    int pc = idx >> 16;          // plane = b*48 + ch
    int ch = pc % CC, bb = pc / CC;
    int r = p >> 8, c = p & 255;
    float v = 0.f;
    if (r < 255 && c < 255) {
        const float* xp = x + (((size_t)bb * 255 + r) * 255 + c) * 4;
        v = b[ch];
        #pragma unroll
        for (int i = 0; i < 4; i++) v += xp[i] * w[i * CC + ch];
    }
    out[idx] = v;
}

// --------------------------- analysis filter bank ---------------------------
// convolve along last axis, stride 2, symmetric pad
__global__ void afb_row(const float* __restrict__ in, float* __restrict__ lo,
                        float* __restrict__ hi, int R, int N, int O, int padL) {
    int idx = blockIdx.x * blockDim.x + threadIdx.x;
    if (idx >= PP * R * O) return;
    int k  = idx % O;
    int pr = idx / O;
    const float* row = in + (size_t)pr * N;
    float a = 0.f, bv = 0.f;
    #pragma unroll
    for (int t = 0; t < 12; t++) {
        int m = symref(2 * k + t - padL, N);
        float v = row[m];
        a  += v * DLO[11 - t];
        bv += v * DHI[11 - t];
    }
    lo[(size_t)pr * O + k] = a;
    hi[(size_t)pr * O + k] = bv;
}

// convolve along row axis (-2), stride 2, symmetric pad
__global__ void afb_col(const float* __restrict__ in, float* __restrict__ lo,
                        float* __restrict__ hi, int Nr, int Nc, int Or, int padL) {
    int idx = blockIdx.x * blockDim.x + threadIdx.x;
    if (idx >= PP * Or * Nc) return;
    int c = idx % Nc;
    int rest = idx / Nc;
    int k = rest % Or;
    int p = rest / Or;
    const float* pl = in + (size_t)p * Nr * Nc;
    float a = 0.f, bv = 0.f;
    #pragma unroll
    for (int t = 0; t < 12; t++) {
        int m = symref(2 * k + t - padL, Nr);
        float v = pl[(size_t)m * Nc + c];
        a  += v * DLO[11 - t];
        bv += v * DHI[11 - t];
    }
    size_t ob = ((size_t)p * Or + k) * Nc + c;
    lo[ob] = a;
    hi[ob] = bv;
}

// --------------------------- synthesis filter bank --------------------------
// along row axis (-2): inputs n rows, output 2n-10 rows
__global__ void sfb_col(const float* __restrict__ lo, const float* __restrict__ hi,
                        float* __restrict__ out, int n, int Nc,
                        long lo_ps, int lo_rs, long hi_ps, int hi_rs) {
    int Or = 2 * n - 10;
    int idx = blockIdx.x * blockDim.x + threadIdx.x;
    if (idx >= PP * Or * Nc) return;
    int c = idx % Nc;
    int rest = idx / Nc;
    int j = rest % Or;
    int p = rest / Or;
    const float* lp = lo + (size_t)p * lo_ps + c;
    const float* hp = hi + (size_t)p * hi_ps + c;
    float acc = 0.f;
    #pragma unroll
    for (int t = 0; t < 12; t++) {
        int s = j + t;
        if (s & 1) {
            int m = (s - 1) >> 1;   // always in [0, n)
            acc += lp[(size_t)m * lo_rs] * DLO[t] + hp[(size_t)m * hi_rs] * DHI[t];
        }
    }
    out[((size_t)p * Or + j) * Nc + c] = acc;
}

// along last axis (-1): inputs width n, output width 2n-10
__global__ void sfb_row(const float* __restrict__ lo, const float* __restrict__ hi,
                        float* __restrict__ out, int R, int n,
                        long lo_ps, int lo_rs, long hi_ps, int hi_rs) {
    int Ow = 2 * n - 10;
    int idx = blockIdx.x * blockDim.x + threadIdx.x;
    if (idx >= PP * R * Ow) return;
    int j = idx % Ow;
    int rest = idx / Ow;
    int r = rest % R;
    int p = rest / R;
    const float* lp = lo + (size_t)p * lo_ps + (size_t)r * lo_rs;
    const float* hp = hi + (size_t)p * hi_ps + (size_t)r * hi_rs;
    float acc = 0.f;
    #pragma unroll
    for (int t = 0; t < 12; t++) {
        int s = j + t;
        if (s & 1) {
            int m = (s - 1) >> 1;
            acc += lp[m] * DLO[t] + hp[m] * DHI[t];
        }
    }
    out[((size_t)p * R + r) * Ow + j] = acc;
}

// --------------------- per-pixel 48x48 channel mix (41x41) ------------------
// t,out: (B,C,41,41) plane-major; w: (i,o,41,41) for one band
__global__ void mix_kernel(const float* __restrict__ t, const float* __restrict__ w,
                           float* __restrict__ out) {
    __shared__ float ws[2304];   // ws[i*48+o]
    __shared__ float ts[384];    // ts[b*48+i]
    int pix = blockIdx.x;        // 0..1680
    int tid = threadIdx.x;       // 384
    for (int j = tid; j < 2304; j += 384) ws[j] = w[(size_t)j * PIX3 + pix];
    ts[tid] = t[(size_t)tid * PIX3 + pix];
    __syncthreads();
    int b = tid / 48, o = tid % 48;
    float acc = 0.f;
    #pragma unroll
    for (int i = 0; i < 48; i++) acc += ts[b * 48 + i] * ws[i * 48 + o];
    out[(size_t)tid * PIX3 + pix] = acc;
}

// ------------------ pointwise conv + residual add + gelu --------------------
// h (in/out), h1: (B,48,256,256); cw: (o,i); in-place on h (per-pixel threads)
__global__ void pw_kernel(float* __restrict__ h, const float* __restrict__ h1,
                          const float* __restrict__ cw, const float* __restrict__ cb,
                          int do_gelu) {
    __shared__ float ws[2304];   // ws[i*48+o] = cw[o*48+i]
    __shared__ float bs[48];
    int tid = threadIdx.x;       // 256
    for (int j = tid; j < 2304; j += 256) {
        int o = j / 48, i = j % 48;
        ws[i * 48 + o] = cw[j];
    }
    if (tid < 48) bs[tid] = cb[tid];
    __syncthreads();
    int q = blockIdx.x * 256 + tid;      // 0..524287
    int bb = q >> 16, p = q & 65535;
    size_t base = ((size_t)bb * CC) * HW + p;
    float acc[48];
    #pragma unroll
    for (int o = 0; o < 48; o++) acc[o] = bs[o];
    for (int i = 0; i < 48; i++) {
        float v = h[base + (size_t)i * HW];
        #pragma unroll
        for (int o = 0; o < 48; o++) acc[o] += v * ws[i * 48 + o];
    }
    #pragma unroll
    for (int o = 0; o < 48; o++) {
        float y = acc[o] + h1[base + (size_t)o * HW];
        if (do_gelu) y = gelu_f(y);
        h[base + (size_t)o * HW] = y;
    }
}

// -------------------------- fused fc1+gelu+fc2 head --------------------------
__global__ void head_kernel(const float* __restrict__ h, const float* __restrict__ w1,
                            const float* __restrict__ b1, const float* __restrict__ w2,
                            const float* __restrict__ b2, float* __restrict__ out) {
    __shared__ float w1s[48 * 64];
    __shared__ float b1s[64];
    __shared__ float w2s[64];
    int tid = threadIdx.x;       // 256
    for (int j = tid; j < 3072; j += 256) w1s[j] = w1[j];
    if (tid < 64) { b1s[tid] = b1[tid]; w2s[tid] = w2[tid]; }
    __syncthreads();
    int q = blockIdx.x * 256 + tid;
    if (q >= 8 * 255 * 255) return;
    int c = q % 255;
    int t2 = q / 255;
    int r = t2 % 255;
    int bb = t2 / 255;
    size_t base = ((size_t)bb * CC) * HW + (size_t)r * 256 + c;
    float acc[64];
    #pragma unroll
    for (int j = 0; j < 64; j++) acc[j] = b1s[j];
    for (int i = 0; i < 48; i++) {
        float v = h[base + (size_t)i * HW];
        #pragma unroll
        for (int j = 0; j < 64; j++) acc[j] += v * w1s[i * 64 + j];
    }
    float o = b2[0];
    #pragma unroll
    for (int j = 0; j < 64; j++) o += gelu_f(acc[j]) * w2s[j];
    out[q] = o;
}

// ---------------------------------- launch ----------------------------------
static inline int grd(long n, int bs) { return (int)((n + bs - 1) / bs); }

extern "C" void kernel_launch(void* const* d_in, const int* in_sizes, int n_in,
                              void* d_out, int out_size) {
    const float* x     = (const float*)d_in[0];
    const float* fc0_w = (const float*)d_in[1];
    const float* fc0_b = (const float*)d_in[2];
    const float* wc[4] = { (const float*)d_in[3], (const float*)d_in[4],
                           (const float*)d_in[5], (const float*)d_in[6] };
    const float* cw    = (const float*)d_in[7];
    const float* cb    = (const float*)d_in[8];
    const float* fc1_w = (const float*)d_in[9];
    const float* fc1_b = (const float*)d_in[10];
    const float* fc2_w = (const float*)d_in[11];
    const float* fc2_b = (const float*)d_in[12];
    float* out = (float*)d_out;

    float *h, *h1, *lo, *hi, *ll1, *lh1, *hl1, *hh1, *ll2, *lh2, *hl2, *hh2, *b3;
    cudaGetSymbolAddress((void**)&h,   g_h);
    cudaGetSymbolAddress((void**)&h1,  g_h1);
    cudaGetSymbolAddress((void**)&lo,  g_lo);
    cudaGetSymbolAddress((void**)&hi,  g_hi);
    cudaGetSymbolAddress((void**)&ll1, g_ll1);
    cudaGetSymbolAddress((void**)&lh1, g_lh1);
    cudaGetSymbolAddress((void**)&hl1, g_hl1);
    cudaGetSymbolAddress((void**)&hh1, g_hh1);
    cudaGetSymbolAddress((void**)&ll2, g_ll2);
    cudaGetSymbolAddress((void**)&lh2, g_lh2);
    cudaGetSymbolAddress((void**)&hl2, g_hl2);
    cudaGetSymbolAddress((void**)&hh2, g_hh2);
    cudaGetSymbolAddress((void**)&b3,  g_b3);

    fc0_kernel<<<grd((long)PP * HW, 256), 256>>>(x, fc0_w, fc0_b, h);

    for (int layer = 0; layer < 4; layer++) {
        // ---------------- forward DWT (3 levels) ----------------
        afb_row<<<grd((long)PP * N1 * O1, 256), 256>>>(h,  lo, hi, N1, N1, O1, 10);
        afb_col<<<grd((long)PP * O1 * O1, 256), 256>>>(lo, ll1, lh1, N1, O1, O1, 10);
        afb_col<<<grd((long)PP * O1 * O1, 256), 256>>>(hi, hl1, hh1, N1, O1, O1, 10);

        afb_row<<<grd((long)PP * O1 * O2, 256), 256>>>(ll1, lo, hi, O1, N2, O2, 10);
        afb_col<<<grd((long)PP * O2 * O2, 256), 256>>>(lo, ll2, lh2, O1, O2, O2, 10);
        afb_col<<<grd((long)PP * O2 * O2, 256), 256>>>(hi, hl2, hh2, O1, O2, O2, 10);

        afb_row<<<grd((long)PP * O2 * O3, 256), 256>>>(ll2, lo, hi, O2, N3, O3, 10);
        afb_col<<<grd((long)PP * O3 * O3, 256), 256>>>(lo, b3 + 0L*B3SZ, b3 + 1L*B3SZ, O2, O3, O3, 10);
        afb_col<<<grd((long)PP * O3 * O3, 256), 256>>>(hi, b3 + 2L*B3SZ, b3 + 3L*B3SZ, O2, O3, O3, 10);

        // ---------------- coarsest-level channel mix ----------------
        const float* wcp = wc[layer];
        mix_kernel<<<PIX3, 384>>>(b3 + 0L*B3SZ, wcp + 0L*WBAND, b3 + 4L*B3SZ);
        mix_kernel<<<PIX3, 384>>>(b3 + 1L*B3SZ, wcp + 1L*WBAND, b3 + 5L*B3SZ);
        mix_kernel<<<PIX3, 384>>>(b3 + 2L*B3SZ, wcp + 2L*WBAND, b3 + 6L*B3SZ);
        mix_kernel<<<PIX3, 384>>>(b3 + 3L*B3SZ, wcp + 3L*WBAND, b3 + 7L*B3SZ);

        // ---------------- inverse DWT ----------------
        // level 3: 41 -> 72
        sfb_col<<<grd((long)PP * 72 * O3, 256), 256>>>(b3 + 4L*B3SZ, b3 + 5L*B3SZ, lo,
                                                        O3, O3, PIX3, O3, PIX3, O3);
        sfb_col<<<grd((long)PP * 72 * O3, 256), 256>>>(b3 + 6L*B3SZ, b3 + 7L*B3SZ, hi,
                                                        O3, O3, PIX3, O3, PIX3, O3);
        sfb_row<<<grd((long)PP * 72 * 72, 256), 256>>>(lo, hi, ll2, 72, O3,
                                                        72L*O3, O3, 72L*O3, O3);
        // level 2: 72 -> 134
        sfb_col<<<grd((long)PP * 134 * O2, 256), 256>>>(ll2, lh2, lo, O2, O2,
                                                         (long)O2*O2, O2, (long)O2*O2, O2);
        sfb_col<<<grd((long)PP * 134 * O2, 256), 256>>>(hl2, hh2, hi, O2, O2,
                                                         (long)O2*O2, O2, (long)O2*O2, O2);
        sfb_row<<<grd((long)PP * 134 * 134, 256), 256>>>(lo, hi, h1, 134, O2,
                                                          134L*O2, O2, 134L*O2, O2);
        // level 1: 133 (crop of 134) -> 256
        sfb_col<<<grd((long)PP * 256 * O1, 256), 256>>>(h1, lh1, lo, O1, O1,
                                                         134L*134, 134, (long)O1*O1, O1);
        sfb_col<<<grd((long)PP * 256 * O1, 256), 256>>>(hl1, hh1, hi, O1, O1,
                                                         (long)O1*O1, O1, (long)O1*O1, O1);
        sfb_row<<<grd((long)PP * 256 * 256, 256), 256>>>(lo, hi, h1, 256, O1,
                                                          256L*O1, O1, 256L*O1, O1);

        // ---------------- pointwise conv + add + gelu ----------------
        pw_kernel<<<2048, 256>>>(h, h1, cw + (size_t)layer * 2304,
                                 cb + (size_t)layer * 48, layer < 3 ? 1 : 0);
    }

    head_kernel<<<grd(8L * 255 * 255, 256), 256>>>(h, fc1_w, fc1_b, fc2_w, fc2_b, out);
}

// round 2
// speedup vs baseline: 1.2135x; 1.2135x over previous
#include <cuda_runtime.h>
#include <math.h>

#define BB 8
#define CC 48
#define PP (BB*CC)          // 384 planes
#define N1 256
#define O1 133
#define N2 133
#define O2 72
#define N3 72
#define O3 41
#define HW (N1*N1)          // 65536
#define PIX3 (O3*O3)        // 1681
#define B3SZ (PP*PIX3)      // 645504

__constant__ float DLO[12] = {
    -0.00107730108499558f, 0.004777257511010651f, 0.0005538422009938016f,
    -0.031582039318031156f, 0.02752286553001629f, 0.09750160558707936f,
    -0.12976686756709563f, -0.22626469396516913f, 0.3152503517092432f,
    0.7511339080215775f, 0.4946238903983854f, 0.11154074335008017f };
__constant__ float DHI[12] = {
    -0.11154074335008017f, 0.4946238903983854f, -0.7511339080215775f,
    0.3152503517092432f, 0.22626469396516913f, -0.12976686756709563f,
    -0.09750160558707936f, 0.02752286553001629f, 0.031582039318031156f,
    0.0005538422009938016f, -0.004777257511010651f, -0.00107730108499558f };

// ------------------- scratch arena (static device memory) -------------------
__device__ float g_h  [PP*HW];
__device__ float g_h1 [PP*HW];      // also holds 134x134 IDWT intermediate
__device__ float g_lo [PP*N1*O1];   // generic row/col scratch (max 256x133)
__device__ float g_hi [PP*N1*O1];
__device__ float g_ll1[PP*O1*O1];
__device__ float g_lh1[PP*O1*O1];
__device__ float g_hl1[PP*O1*O1];
__device__ float g_hh1[PP*O1*O1];
__device__ float g_ll2[PP*O2*O2];
__device__ float g_lh2[PP*O2*O2];
__device__ float g_hl2[PP*O2*O2];
__device__ float g_hh2[PP*O2*O2];
__device__ float g_b3 [8*B3SZ];     // slots: 0..3 raw ll,lh,hl,hh ; 4..7 mixed
__device__ float g_wT [9216*PIX3];  // transposed mix weights (one layer)

// --------------------------- f32x2 packed helpers ---------------------------
__device__ __forceinline__ unsigned long long pack2(float x, float y) {
    unsigned long long r;
    asm("mov.b64 %0, {%1, %2};" : "=l"(r) : "f"(x), "f"(y));
    return r;
}
__device__ __forceinline__ void unpack2(unsigned long long v, float &x, float &y) {
    asm("mov.b64 {%0, %1}, %2;" : "=f"(x), "=f"(y) : "l"(v));
}
__device__ __forceinline__ unsigned long long ffma2(unsigned long long a,
                                                    unsigned long long b,
                                                    unsigned long long c) {
    unsigned long long d;
    asm("fma.rn.f32x2 %0, %1, %2, %3;" : "=l"(d) : "l"(a), "l"(b), "l"(c));
    return d;
}

__device__ __forceinline__ float gelu_f(float x) {
    return 0.5f * x * (1.0f + erff(x * 0.7071067811865475f));
}

// ------------------------------ fc0 + pad -----------------------------------
__global__ void fc0_kernel(const float* __restrict__ x,
                           const float* __restrict__ w,
                           const float* __restrict__ b,
                           float* __restrict__ out) {
    int idx = blockIdx.x * blockDim.x + threadIdx.x;
    if (idx >= PP * HW) return;
    int p  = idx & (HW - 1);
    int pc = idx >> 16;          // plane = b*48 + ch
    int ch = pc % CC, bb = pc / CC;
    int r = p >> 8, c = p & 255;
    float v = 0.f;
    if (r < 255 && c < 255) {
        const float* xp = x + (((size_t)bb * 255 + r) * 255 + c) * 4;
        v = b[ch];
        #pragma unroll
        for (int i = 0; i < 4; i++) v += xp[i] * w[i * CC + ch];
    }
    out[idx] = v;
}

// --------------------------- analysis filter bank ---------------------------
// conv along last axis, stride 2, symmetric pad (single-fold reflection)
// grid: (ceil(O/64), R, PP)
__global__ void afb_row(const float* __restrict__ in, float* __restrict__ lo,
                        float* __restrict__ hi, int N, int O) {
    int k = blockIdx.x * 64 + threadIdx.x;
    if (k >= O) return;
    int r = blockIdx.y, p = blockIdx.z;
    const float* row = in + ((size_t)p * gridDim.y + r) * N;
    float a = 0.f, bv = 0.f;
    int i0 = 2 * k - 10;
    #pragma unroll
    for (int t = 0; t < 12; t++) {
        int i = i0 + t;
        i = (i < 0)  ? -1 - i : i;
        i = (i >= N) ? 2 * N - 1 - i : i;
        float v = row[i];
        a  += v * DLO[11 - t];
        bv += v * DHI[11 - t];
    }
    size_t ob = ((size_t)p * gridDim.y + r) * O + k;
    lo[ob] = a;
    hi[ob] = bv;
}

// conv along row axis (-2), stride 2, symmetric pad
// grid: (ceil(Nc/64), Or, PP)
__global__ void afb_col(const float* __restrict__ in, float* __restrict__ lo,
                        float* __restrict__ hi, int Nr, int Nc) {
    int c = blockIdx.x * 64 + threadIdx.x;
    if (c >= Nc) return;
    int k = blockIdx.y, p = blockIdx.z;
    const float* pl = in + (size_t)p * Nr * Nc;
    float a = 0.f, bv = 0.f;
    int i0 = 2 * k - 10;
    #pragma unroll
    for (int t = 0; t < 12; t++) {
        int i = i0 + t;
        i = (i < 0)   ? -1 - i : i;
        i = (i >= Nr) ? 2 * Nr - 1 - i : i;
        float v = pl[(size_t)i * Nc + c];
        a  += v * DLO[11 - t];
        bv += v * DHI[11 - t];
    }
    size_t ob = ((size_t)p * gridDim.y + k) * Nc + c;
    lo[ob] = a;
    hi[ob] = bv;
}

// --------------------------- synthesis filter bank --------------------------
// (j+t) odd => 6 taps: m = (j>>1)+k, coeff D[2k + 1-(j&1)]
// grid: (ceil(Nc/64), Or, PP)
__global__ void sfb_col(const float* __restrict__ lo, const float* __restrict__ hi,
                        float* __restrict__ out, int Nc,
                        long lo_ps, int lo_rs, long hi_ps, int hi_rs) {
    int c = blockIdx.x * 64 + threadIdx.x;
    if (c >= Nc) return;
    int j = blockIdx.y, p = blockIdx.z;
    const float* lp = lo + (size_t)p * lo_ps + c;
    const float* hp = hi + (size_t)p * hi_ps + c;
    int mb = j >> 1, sel = 1 - (j & 1);
    float acc = 0.f;
    #pragma unroll
    for (int kk = 0; kk < 6; kk++) {
        acc += lp[(size_t)(mb + kk) * lo_rs] * DLO[2 * kk + sel]
             + hp[(size_t)(mb + kk) * hi_rs] * DHI[2 * kk + sel];
    }
    out[((size_t)p * gridDim.y + j) * Nc + c] = acc;
}

// grid: (ceil(Ow/64), R, PP)
__global__ void sfb_row(const float* __restrict__ lo, const float* __restrict__ hi,
                        float* __restrict__ out, int Ow,
                        long lo_ps, int lo_rs, long hi_ps, int hi_rs) {
    int j = blockIdx.x * 64 + threadIdx.x;
    if (j >= Ow) return;
    int r = blockIdx.y, p = blockIdx.z;
    const float* lp = lo + (size_t)p * lo_ps + (size_t)r * lo_rs;
    const float* hp = hi + (size_t)p * hi_ps + (size_t)r * hi_rs;
    int mb = j >> 1, sel = 1 - (j & 1);
    float acc = 0.f;
    #pragma unroll
    for (int kk = 0; kk < 6; kk++)
        acc += lp[mb + kk] * DLO[2 * kk + sel] + hp[mb + kk] * DHI[2 * kk + sel];
    out[((size_t)p * gridDim.y + r) * Ow + j] = acc;
}

// -------------------- weight transpose for the mix einsum --------------------
// w: [9216][1681] -> wT: [1681][9216]
__global__ void transpose_w(const float* __restrict__ w, float* __restrict__ wT) {
    __shared__ float tile[32][33];
    int j0 = blockIdx.y * 32, p0 = blockIdx.x * 32;
    int tx = threadIdx.x, ty = threadIdx.y;   // 32 x 8
    #pragma unroll
    for (int dy = 0; dy < 32; dy += 8) {
        int j = j0 + ty + dy, p = p0 + tx;
        tile[ty + dy][tx] = (j < 9216 && p < PIX3) ? w[(size_t)j * PIX3 + p] : 0.f;
    }
    __syncthreads();
    #pragma unroll
    for (int dy = 0; dy < 32; dy += 8) {
        int p = p0 + ty + dy, j = j0 + tx;
        if (p < PIX3 && j < 9216) wT[(size_t)p * 9216 + j] = tile[tx][ty + dy];
    }
}

// --------------------- per-pixel 48x48 channel mix (41x41) ------------------
// grid: (PIX3, 4 bands), block 384
__global__ void mix_kernel(const float* __restrict__ b3in, const float* __restrict__ wT,
                           float* __restrict__ b3out) {
    __shared__ float ws[2304];   // ws[i*48+o]
    __shared__ float ts[384];    // ts[b*48+i]
    int pix = blockIdx.x, band = blockIdx.y, tid = threadIdx.x;
    const float* wp = wT + (size_t)pix * 9216 + (size_t)band * 2304;
    for (int j = tid; j < 2304; j += 384) ws[j] = wp[j];
    ts[tid] = b3in[(size_t)band * B3SZ + (size_t)tid * PIX3 + pix];
    __syncthreads();
    int b = tid / 48, o = tid - b * 48;
    const float* tb = ts + b * 48;
    float acc = 0.f;
    #pragma unroll
    for (int i = 0; i < 48; i++) acc += tb[i] * ws[i * 48 + o];
    b3out[(size_t)band * B3SZ + (size_t)tid * PIX3 + pix] = acc;
}

// ------------------ pointwise conv + residual add + gelu --------------------
// block 256 = 4 output-groups x 64 pixel-groups(4 px each); grid 2048
__global__ void pw_kernel(float* __restrict__ h, const float* __restrict__ h1,
                          const float* __restrict__ cw, const float* __restrict__ cb,
                          int do_gelu) {
    __shared__ unsigned long long ws2[2304];   // (w,w) pairs, [i*48+o]
    __shared__ float bs[48];
    int tid = threadIdx.x;
    for (int j = tid; j < 2304; j += 256) {
        int o = j / 48, i = j - o * 48;
        float w = cw[j];
        ws2[i * 48 + o] = pack2(w, w);
    }
    if (tid < 48) bs[tid] = cb[tid];
    __syncthreads();
    int og = tid >> 6;                 // 0..3 -> outputs [og*12, og*12+12)
    int pq = tid & 63;
    int bx = blockIdx.x;               // 0..2047
    int bb = bx >> 8;
    int p0 = ((bx & 255) << 8) + (pq << 2);
    size_t base = ((size_t)bb * CC) * HW + p0;
    unsigned long long acc[12][2];
    #pragma unroll
    for (int o = 0; o < 12; o++) {
        float b = bs[og * 12 + o];
        acc[o][0] = pack2(b, b);
        acc[o][1] = acc[o][0];
    }
    for (int i = 0; i < 48; i++) {
        ulonglong2 v = *(const ulonglong2*)(h + base + (size_t)i * HW);
        #pragma unroll
        for (int o = 0; o < 12; o++) {
            unsigned long long w2 = ws2[i * 48 + og * 12 + o];
            acc[o][0] = ffma2(v.x, w2, acc[o][0]);
            acc[o][1] = ffma2(v.y, w2, acc[o][1]);
        }
    }
    __syncthreads();   // all warps done reading h before any writes h
    #pragma unroll
    for (int o = 0; o < 12; o++) {
        int oc = og * 12 + o;
        float4 r = *(const float4*)(h1 + base + (size_t)oc * HW);
        float a, b, c, d;
        unpack2(acc[o][0], a, b);
        unpack2(acc[o][1], c, d);
        a += r.x; b += r.y; c += r.z; d += r.w;
        if (do_gelu) { a = gelu_f(a); b = gelu_f(b); c = gelu_f(c); d = gelu_f(d); }
        *(float4*)(h + base + (size_t)oc * HW) = make_float4(a, b, c, d);
    }
}

// -------------------------- fused fc1+gelu+fc2 head --------------------------
__global__ void head_kernel(const float* __restrict__ h, const float* __restrict__ w1,
                            const float* __restrict__ b1, const float* __restrict__ w2,
                            const float* __restrict__ b2, float* __restrict__ out) {
    __shared__ unsigned long long w1s[1536];   // w1 as (2j,2j+1) pairs per i
    __shared__ float b1s[64];
    __shared__ float w2s[64];
    int tid = threadIdx.x;   // 256
    const unsigned long long* w1u = (const unsigned long long*)w1;
    for (int j = tid; j < 1536; j += 256) w1s[j] = w1u[j];
    if (tid < 64) { b1s[tid] = b1[tid]; w2s[tid] = w2[tid]; }
    __syncthreads();
    int q = blockIdx.x * 256 + tid;
    if (q >= 8 * 255 * 255) return;
    int c = q % 255;
    int t2 = q / 255;
    int r = t2 % 255;
    int bb = t2 / 255;
    size_t base = ((size_t)bb * CC) * HW + (size_t)r * 256 + c;
    unsigned long long acc[32];
    #pragma unroll
    for (int j = 0; j < 32; j++) acc[j] = pack2(b1s[2 * j], b1s[2 * j + 1]);
    for (int i = 0; i < 48; i++) {
        float v = h[base + (size_t)i * HW];
        unsigned long long vv = pack2(v, v);
        #pragma unroll
        for (int j = 0; j < 32; j++) acc[j] = ffma2(vv, w1s[i * 32 + j], acc[j]);
    }
    float o = b2[0];
    #pragma unroll
    for (int j = 0; j < 32; j++) {
        float a, b;
        unpack2(acc[j], a, b);
        o += gelu_f(a) * w2s[2 * j] + gelu_f(b) * w2s[2 * j + 1];
    }
    out[q] = o;
}

// ---------------------------------- launch ----------------------------------
static inline int grd(long n, int bs) { return (int)((n + bs - 1) / bs); }

extern "C" void kernel_launch(void* const* d_in, const int* in_sizes, int n_in,
                              void* d_out, int out_size) {
    const float* x     = (const float*)d_in[0];
    const float* fc0_w = (const float*)d_in[1];
    const float* fc0_b = (const float*)d_in[2];
    const float* wc[4] = { (const float*)d_in[3], (const float*)d_in[4],
                           (const float*)d_in[5], (const float*)d_in[6] };
    const float* cw    = (const float*)d_in[7];
    const float* cb    = (const float*)d_in[8];
    const float* fc1_w = (const float*)d_in[9];
    const float* fc1_b = (const float*)d_in[10];
    const float* fc2_w = (const float*)d_in[11];
    const float* fc2_b = (const float*)d_in[12];
    float* out = (float*)d_out;

    float *h, *h1, *lo, *hi, *ll1, *lh1, *hl1, *hh1, *ll2, *lh2, *hl2, *hh2, *b3, *wT;
    cudaGetSymbolAddress((void**)&h,   g_h);
    cudaGetSymbolAddress((void**)&h1,  g_h1);
    cudaGetSymbolAddress((void**)&lo,  g_lo);
    cudaGetSymbolAddress((void**)&hi,  g_hi);
    cudaGetSymbolAddress((void**)&ll1, g_ll1);
    cudaGetSymbolAddress((void**)&lh1, g_lh1);
    cudaGetSymbolAddress((void**)&hl1, g_hl1);
    cudaGetSymbolAddress((void**)&hh1, g_hh1);
    cudaGetSymbolAddress((void**)&ll2, g_ll2);
    cudaGetSymbolAddress((void**)&lh2, g_lh2);
    cudaGetSymbolAddress((void**)&hl2, g_hl2);
    cudaGetSymbolAddress((void**)&hh2, g_hh2);
    cudaGetSymbolAddress((void**)&b3,  g_b3);
    cudaGetSymbolAddress((void**)&wT,  g_wT);

    fc0_kernel<<<grd((long)PP * HW, 256), 256>>>(x, fc0_w, fc0_b, h);

    for (int layer = 0; layer < 4; layer++) {
        // ---------------- forward DWT (3 levels) ----------------
        afb_row<<<dim3(grd(O1,64), N1, PP), 64>>>(h,  lo, hi, N1, O1);
        afb_col<<<dim3(grd(O1,64), O1, PP), 64>>>(lo, ll1, lh1, N1, O1);
        afb_col<<<dim3(grd(O1,64), O1, PP), 64>>>(hi, hl1, hh1, N1, O1);

        afb_row<<<dim3(grd(O2,64), O1, PP), 64>>>(ll1, lo, hi, N2, O2);
        afb_col<<<dim3(grd(O2,64), O2, PP), 64>>>(lo, ll2, lh2, O1, O2);
        afb_col<<<dim3(grd(O2,64), O2, PP), 64>>>(hi, hl2, hh2, O1, O2);

        afb_row<<<dim3(grd(O3,64), O2, PP), 64>>>(ll2, lo, hi, N3, O3);
        afb_col<<<dim3(grd(O3,64), O3, PP), 64>>>(lo, b3 + 0L*B3SZ, b3 + 1L*B3SZ, O2, O3);
        afb_col<<<dim3(grd(O3,64), O3, PP), 64>>>(hi, b3 + 2L*B3SZ, b3 + 3L*B3SZ, O2, O3);

        // ---------------- coarsest-level channel mix ----------------
        transpose_w<<<dim3(grd(PIX3,32), grd(9216,32)), dim3(32,8)>>>(wc[layer], wT);
        mix_kernel<<<dim3(PIX3, 4), 384>>>(b3, wT, b3 + 4L*B3SZ);

        // ---------------- inverse DWT ----------------
        // level 3: 41 -> 72
        sfb_col<<<dim3(grd(O3,64), 72, PP), 64>>>(b3 + 4L*B3SZ, b3 + 5L*B3SZ, lo,
                                                   O3, PIX3, O3, PIX3, O3);
        sfb_col<<<dim3(grd(O3,64), 72, PP), 64>>>(b3 + 6L*B3SZ, b3 + 7L*B3SZ, hi,
                                                   O3, PIX3, O3, PIX3, O3);
        sfb_row<<<dim3(grd(72,64), 72, PP), 64>>>(lo, hi, ll2, 72,
                                                   72L*O3, O3, 72L*O3, O3);
        // level 2: 72 -> 134
        sfb_col<<<dim3(grd(O2,64), 134, PP), 64>>>(ll2, lh2, lo, O2,
                                                    (long)O2*O2, O2, (long)O2*O2, O2);
        sfb_col<<<dim3(grd(O2,64), 134, PP), 64>>>(hl2, hh2, hi, O2,
                                                    (long)O2*O2, O2, (long)O2*O2, O2);
        sfb_row<<<dim3(grd(134,64), 134, PP), 64>>>(lo, hi, h1, 134,
                                                     134L*O2, O2, 134L*O2, O2);
        // level 1: 133 (crop of 134) -> 256
        sfb_col<<<dim3(grd(O1,64), 256, PP), 64>>>(h1, lh1, lo, O1,
                                                    134L*134, 134, (long)O1*O1, O1);
        sfb_col<<<dim3(grd(O1,64), 256, PP), 64>>>(hl1, hh1, hi, O1,
                                                    (long)O1*O1, O1, (long)O1*O1, O1);
        sfb_row<<<dim3(grd(256,64), 256, PP), 64>>>(lo, hi, h1, 256,
                                                     256L*O1, O1, 256L*O1, O1);

        // ---------------- pointwise conv + add + gelu ----------------
        pw_kernel<<<2048, 256>>>(h, h1, cw + (size_t)layer * 2304,
                                 cb + (size_t)layer * 48, layer < 3 ? 1 : 0);
    }

    head_kernel<<<grd(8L * 255 * 255, 256), 256>>>(h, fc1_w, fc1_b, fc2_w, fc2_b, out);
}

// round 3
// speedup vs baseline: 2.7155x; 2.2377x over previous
#include <cuda_runtime.h>
#include <math.h>

#define BB 8
#define CC 48
#define PP (BB*CC)          // 384 planes
#define N1 256
#define O1 133
#define O2 72
#define O3 41
#define HW (N1*N1)          // 65536
#define PIX3 (O3*O3)        // 1681
#define B3SZ (PP*PIX3)      // 645504
#define SEG 12              // afb_col outputs per thread
#define USEG 8              // sfb_col output-pairs per thread

__constant__ float DLO[12] = {
    -0.00107730108499558f, 0.004777257511010651f, 0.0005538422009938016f,
    -0.031582039318031156f, 0.02752286553001629f, 0.09750160558707936f,
    -0.12976686756709563f, -0.22626469396516913f, 0.3152503517092432f,
    0.7511339080215775f, 0.4946238903983854f, 0.11154074335008017f };
__constant__ float DHI[12] = {
    -0.11154074335008017f, 0.4946238903983854f, -0.7511339080215775f,
    0.3152503517092432f, 0.22626469396516913f, -0.12976686756709563f,
    -0.09750160558707936f, 0.02752286553001629f, 0.031582039318031156f,
    0.0005538422009938016f, -0.004777257511010651f, -0.00107730108499558f };

// ------------------- scratch arena (static device memory) -------------------
__device__ float g_h  [PP*HW];
__device__ float g_h1 [PP*HW];      // also holds 134x134 IDWT intermediate
__device__ float g_lo [PP*N1*O1];   // generic row/col scratch (max 256x133)
__device__ float g_hi [PP*N1*O1];
__device__ float g_ll1[PP*O1*O1];
__device__ float g_lh1[PP*O1*O1];
__device__ float g_hl1[PP*O1*O1];
__device__ float g_hh1[PP*O1*O1];
__device__ float g_ll2[PP*O2*O2];
__device__ float g_lh2[PP*O2*O2];
__device__ float g_hl2[PP*O2*O2];
__device__ float g_hh2[PP*O2*O2];
__device__ float g_b3 [8*B3SZ];     // slots: 0..3 raw ll,lh,hl,hh ; 4..7 mixed
__device__ float g_wT [9216*PIX3];  // transposed mix weights (one layer)

// --------------------------- f32x2 packed helpers ---------------------------
__device__ __forceinline__ unsigned long long pack2(float x, float y) {
    unsigned long long r;
    asm("mov.b64 %0, {%1, %2};" : "=l"(r) : "f"(x), "f"(y));
    return r;
}
__device__ __forceinline__ void unpack2(unsigned long long v, float &x, float &y) {
    asm("mov.b64 {%0, %1}, %2;" : "=f"(x), "=f"(y) : "l"(v));
}
__device__ __forceinline__ unsigned long long ffma2(unsigned long long a,
                                                    unsigned long long b,
                                                    unsigned long long c) {
    unsigned long long d;
    asm("fma.rn.f32x2 %0, %1, %2, %3;" : "=l"(d) : "l"(a), "l"(b), "l"(c));
    return d;
}

__device__ __forceinline__ float gelu_f(float x) {
    return 0.5f * x * (1.0f + erff(x * 0.7071067811865475f));
}

// ------------------------------ fc0 + pad -----------------------------------
__global__ void fc0_kernel(const float* __restrict__ x,
                           const float* __restrict__ w,
                           const float* __restrict__ b,
                           float* __restrict__ out) {
    int idx = blockIdx.x * blockDim.x + threadIdx.x;
    if (idx >= PP * HW) return;
    int p  = idx & (HW - 1);
    int pc = idx >> 16;
    int ch = pc % CC, bb = pc / CC;
    int r = p >> 8, c = p & 255;
    float v = 0.f;
    if (r < 255 && c < 255) {
        const float* xp = x + (((size_t)bb * 255 + r) * 255 + c) * 4;
        v = b[ch];
        #pragma unroll
        for (int i = 0; i < 4; i++) v += xp[i] * w[i * CC + ch];
    }
    out[idx] = v;
}

// ------------------- analysis, row direction (smem-staged) -------------------
// grid (R, PP), block 64. Input row: in + p*in_ps + r*in_rs, length N.
__global__ void afb_row_k(const float* __restrict__ in, float* __restrict__ lo,
                          float* __restrict__ hi, int N, int O, int padR,
                          long in_ps, int in_rs) {
    __shared__ float s[280];
    int r = blockIdx.x, p = blockIdx.y;
    const float* row = in + (size_t)p * in_ps + (size_t)r * in_rs;
    int tid = threadIdx.x;
    int tot = N + 10 + padR;
    for (int i = tid; i < tot; i += 64) {
        int idx = i - 10;
        idx = (idx < 0)  ? -1 - idx : idx;
        idx = (idx >= N) ? 2 * N - 1 - idx : idx;
        s[i] = row[idx];
    }
    __syncthreads();
    size_t ob = ((size_t)p * gridDim.x + r) * O;
    for (int k = tid; k < O; k += 64) {
        float a = 0.f, bv = 0.f;
        int s0 = 2 * k;
        #pragma unroll
        for (int t = 0; t < 12; t++) {
            float v = s[s0 + t];
            a  += v * DLO[11 - t];
            bv += v * DHI[11 - t];
        }
        lo[ob + k] = a;
        hi[ob + k] = bv;
    }
}

// ------------- analysis, col direction (sliding window, 2 inputs) ------------
// grid (ceil(Nc/64), ceil(Or/SEG), 2*PP), block 64.
__global__ void afb_col2(const float* __restrict__ inA, const float* __restrict__ inB,
                         float* __restrict__ loA, float* __restrict__ hiA,
                         float* __restrict__ loB, float* __restrict__ hiB,
                         int Nr, int Nc, int Or) {
    int c = blockIdx.x * 64 + threadIdx.x;
    if (c >= Nc) return;
    int z = blockIdx.z;
    const float* in = (z < PP) ? inA : inB;
    float* lo = (z < PP) ? loA : loB;
    float* hi = (z < PP) ? hiA : hiB;
    int p = (z < PP) ? z : z - PP;
    int k0 = blockIdx.y * SEG;
    const float* base = in + (size_t)p * Nr * Nc + c;
    float w[12];
    #pragma unroll
    for (int t = 0; t < 12; t++) {
        int i = 2 * k0 - 10 + t;
        i = (i < 0)   ? -1 - i : i;
        i = (i >= Nr) ? 2 * Nr - 1 - i : i;
        w[t] = base[(size_t)i * Nc];
    }
    size_t ob = ((size_t)p * Or + k0) * Nc + c;
    #pragma unroll
    for (int s = 0; s < SEG; s++) {
        int k = k0 + s;
        if (k < Or) {
            float a = 0.f, bv = 0.f;
            #pragma unroll
            for (int t = 0; t < 12; t++) {
                a  += w[t] * DLO[11 - t];
                bv += w[t] * DHI[11 - t];
            }
            lo[ob] = a;
            hi[ob] = bv;
        }
        ob += Nc;
        #pragma unroll
        for (int t = 0; t < 10; t++) w[t] = w[t + 2];
        int i2 = 2 * k + 2, i3 = 2 * k + 3;
        i2 = (i2 >= Nr) ? 2 * Nr - 1 - i2 : i2;
        i3 = (i3 >= Nr) ? 2 * Nr - 1 - i3 : i3;
        w[10] = base[(size_t)i2 * Nc];
        w[11] = base[(size_t)i3 * Nc];
    }
}

// ------------- synthesis, col direction (sliding window, 2 pairs) ------------
// grid (ceil(Nc/64), ceil((Or/2)/USEG), 2*PP), block 64. n = input rows.
__global__ void sfb_col2(const float* __restrict__ loA, const float* __restrict__ hiA,
                         const float* __restrict__ loB, const float* __restrict__ hiB,
                         float* __restrict__ outA, float* __restrict__ outB,
                         int n, int Nc, int Or,
                         long loA_ps, int loA_rs, long hiA_ps, int hiA_rs,
                         long loB_ps, int loB_rs, long hiB_ps, int hiB_rs) {
    int c = blockIdx.x * 64 + threadIdx.x;
    if (c >= Nc) return;
    int z = blockIdx.z;
    int p = (z < PP) ? z : z - PP;
    const float* lp;
    const float* hp;
    float* out;
    long lo_rs, hi_rs;
    if (z < PP) {
        lp = loA + (size_t)p * loA_ps + c; hp = hiA + (size_t)p * hiA_ps + c;
        out = outA; lo_rs = loA_rs; hi_rs = hiA_rs;
    } else {
        lp = loB + (size_t)p * loB_ps + c; hp = hiB + (size_t)p * hiB_ps + c;
        out = outB; lo_rs = loB_rs; hi_rs = hiB_rs;
    }
    int u0 = blockIdx.y * USEG;
    float wl[6], wh[6];
    #pragma unroll
    for (int t = 0; t < 6; t++) {
        wl[t] = lp[(size_t)(u0 + t) * lo_rs];
        wh[t] = hp[(size_t)(u0 + t) * hi_rs];
    }
    size_t ob = ((size_t)p * Or + 2 * u0) * Nc + c;
    #pragma unroll
    for (int s = 0; s < USEG; s++) {
        int u = u0 + s;
        if (2 * u < Or) {
            float e = 0.f, o = 0.f;
            #pragma unroll
            for (int kk = 0; kk < 6; kk++) {
                float a = wl[kk], b = wh[kk];
                e += a * DLO[2 * kk + 1] + b * DHI[2 * kk + 1];
                o += a * DLO[2 * kk]     + b * DHI[2 * kk];
            }
            out[ob] = e;
            out[ob + Nc] = o;
        }
        ob += 2 * (size_t)Nc;
        #pragma unroll
        for (int t = 0; t < 5; t++) { wl[t] = wl[t + 1]; wh[t] = wh[t + 1]; }
        int idx = u + 6;
        if (idx < n) {
            wl[5] = lp[(size_t)idx * lo_rs];
            wh[5] = hp[(size_t)idx * hi_rs];
        }
    }
}

// ------------------- synthesis, row direction (smem-staged) ------------------
// grid (R, PP), block 64; input width n, output width Ow = 2n-10.
__global__ void sfb_row_k(const float* __restrict__ lo, const float* __restrict__ hi,
                          float* __restrict__ out, int n, int Ow,
                          long lo_ps, int lo_rs, long hi_ps, int hi_rs) {
    __shared__ float sl[136], sh[136];
    int r = blockIdx.x, p = blockIdx.y;
    const float* lp = lo + (size_t)p * lo_ps + (size_t)r * lo_rs;
    const float* hp = hi + (size_t)p * hi_ps + (size_t)r * hi_rs;
    int tid = threadIdx.x;
    for (int i = tid; i < n; i += 64) { sl[i] = lp[i]; sh[i] = hp[i]; }
    __syncthreads();
    size_t ob = ((size_t)p * gridDim.x + r) * Ow;
    int np = Ow >> 1;
    for (int u = tid; u < np; u += 64) {
        float e = 0.f, o = 0.f;
        #pragma unroll
        for (int kk = 0; kk < 6; kk++) {
            float a = sl[u + kk], b = sh[u + kk];
            e += a * DLO[2 * kk + 1] + b * DHI[2 * kk + 1];
            o += a * DLO[2 * kk]     + b * DHI[2 * kk];
        }
        out[ob + 2 * u] = e;
        out[ob + 2 * u + 1] = o;
    }
}

// -------------------- weight transpose for the mix einsum --------------------
__global__ void transpose_w(const float* __restrict__ w, float* __restrict__ wT) {
    __shared__ float tile[32][33];
    int j0 = blockIdx.y * 32, p0 = blockIdx.x * 32;
    int tx = threadIdx.x, ty = threadIdx.y;   // 32 x 8
    #pragma unroll
    for (int dy = 0; dy < 32; dy += 8) {
        int j = j0 + ty + dy, p = p0 + tx;
        tile[ty + dy][tx] = (j < 9216 && p < PIX3) ? w[(size_t)j * PIX3 + p] : 0.f;
    }
    __syncthreads();
    #pragma unroll
    for (int dy = 0; dy < 32; dy += 8) {
        int p = p0 + ty + dy, j = j0 + tx;
        if (p < PIX3 && j < 9216) wT[(size_t)p * 9216 + j] = tile[tx][ty + dy];
    }
}

// --------------------- per-pixel 48x48 channel mix (41x41) ------------------
__global__ void mix_kernel(const float* __restrict__ b3in, const float* __restrict__ wT,
                           float* __restrict__ b3out) {
    __shared__ float ws[2304];
    __shared__ float ts[384];
    int pix = blockIdx.x, band = blockIdx.y, tid = threadIdx.x;
    const float* wp = wT + (size_t)pix * 9216 + (size_t)band * 2304;
    for (int j = tid; j < 2304; j += 384) ws[j] = wp[j];
    ts[tid] = b3in[(size_t)band * B3SZ + (size_t)tid * PIX3 + pix];
    __syncthreads();
    int b = tid / 48, o = tid - b * 48;
    const float* tb = ts + b * 48;
    float acc = 0.f;
    #pragma unroll
    for (int i = 0; i < 48; i++) acc += tb[i] * ws[i * 48 + o];
    b3out[(size_t)band * B3SZ + (size_t)tid * PIX3 + pix] = acc;
}

// ------------------ pointwise conv + residual add + gelu --------------------
__global__ void pw_kernel(float* __restrict__ h, const float* __restrict__ h1,
                          const float* __restrict__ cw, const float* __restrict__ cb,
                          int do_gelu) {
    __shared__ unsigned long long ws2[2304];
    __shared__ float bs[48];
    int tid = threadIdx.x;
    for (int j = tid; j < 2304; j += 256) {
        int o = j / 48, i = j - o * 48;
        float w = cw[j];
        ws2[i * 48 + o] = pack2(w, w);
    }
    if (tid < 48) bs[tid] = cb[tid];
    __syncthreads();
    int og = tid >> 6;
    int pq = tid & 63;
    int bx = blockIdx.x;
    int bb = bx >> 8;
    int p0 = ((bx & 255) << 8) + (pq << 2);
    size_t base = ((size_t)bb * CC) * HW + p0;
    unsigned long long acc[12][2];
    #pragma unroll
    for (int o = 0; o < 12; o++) {
        float b = bs[og * 12 + o];
        acc[o][0] = pack2(b, b);
        acc[o][1] = acc[o][0];
    }
    for (int i = 0; i < 48; i++) {
        ulonglong2 v = *(const ulonglong2*)(h + base + (size_t)i * HW);
        #pragma unroll
        for (int o = 0; o < 12; o++) {
            unsigned long long w2 = ws2[i * 48 + og * 12 + o];
            acc[o][0] = ffma2(v.x, w2, acc[o][0]);
            acc[o][1] = ffma2(v.y, w2, acc[o][1]);
        }
    }
    __syncthreads();
    #pragma unroll
    for (int o = 0; o < 12; o++) {
        int oc = og * 12 + o;
        float4 r = *(const float4*)(h1 + base + (size_t)oc * HW);
        float a, b, c, d;
        unpack2(acc[o][0], a, b);
        unpack2(acc[o][1], c, d);
        a += r.x; b += r.y; c += r.z; d += r.w;
        if (do_gelu) { a = gelu_f(a); b = gelu_f(b); c = gelu_f(c); d = gelu_f(d); }
        *(float4*)(h + base + (size_t)oc * HW) = make_float4(a, b, c, d);
    }
}

// -------------------------- fused fc1+gelu+fc2 head --------------------------
__global__ void head_kernel(const float* __restrict__ h, const float* __restrict__ w1,
                            const float* __restrict__ b1, const float* __restrict__ w2,
                            const float* __restrict__ b2, float* __restrict__ out) {
    __shared__ unsigned long long w1s[1536];
    __shared__ float b1s[64];
    __shared__ float w2s[64];
    int tid = threadIdx.x;
    const unsigned long long* w1u = (const unsigned long long*)w1;
    for (int j = tid; j < 1536; j += 256) w1s[j] = w1u[j];
    if (tid < 64) { b1s[tid] = b1[tid]; w2s[tid] = w2[tid]; }
    __syncthreads();
    int q = blockIdx.x * 256 + tid;
    if (q >= 8 * 255 * 255) return;
    int c = q % 255;
    int t2 = q / 255;
    int r = t2 % 255;
    int bb = t2 / 255;
    size_t base = ((size_t)bb * CC) * HW + (size_t)r * 256 + c;
    unsigned long long acc[32];
    #pragma unroll
    for (int j = 0; j < 32; j++) acc[j] = pack2(b1s[2 * j], b1s[2 * j + 1]);
    for (int i = 0; i < 48; i++) {
        float v = h[base + (size_t)i * HW];
        unsigned long long vv = pack2(v, v);
        #pragma unroll
        for (int j = 0; j < 32; j++) acc[j] = ffma2(vv, w1s[i * 32 + j], acc[j]);
    }
    float o = b2[0];
    #pragma unroll
    for (int j = 0; j < 32; j++) {
        float a, b;
        unpack2(acc[j], a, b);
        o += gelu_f(a) * w2s[2 * j] + gelu_f(b) * w2s[2 * j + 1];
    }
    out[q] = o;
}

// ---------------------------------- launch ----------------------------------
static inline int grd(long n, int bs) { return (int)((n + bs - 1) / bs); }

extern "C" void kernel_launch(void* const* d_in, const int* in_sizes, int n_in,
                              void* d_out, int out_size) {
    const float* x     = (const float*)d_in[0];
    const float* fc0_w = (const float*)d_in[1];
    const float* fc0_b = (const float*)d_in[2];
    const float* wc[4] = { (const float*)d_in[3], (const float*)d_in[4],
                           (const float*)d_in[5], (const float*)d_in[6] };
    const float* cw    = (const float*)d_in[7];
    const float* cb    = (const float*)d_in[8];
    const float* fc1_w = (const float*)d_in[9];
    const float* fc1_b = (const float*)d_in[10];
    const float* fc2_w = (const float*)d_in[11];
    const float* fc2_b = (const float*)d_in[12];
    float* out = (float*)d_out;

    float *h, *h1, *lo, *hi, *ll1, *lh1, *hl1, *hh1, *ll2, *lh2, *hl2, *hh2, *b3, *wT;
    cudaGetSymbolAddress((void**)&h,   g_h);
    cudaGetSymbolAddress((void**)&h1,  g_h1);
    cudaGetSymbolAddress((void**)&lo,  g_lo);
    cudaGetSymbolAddress((void**)&hi,  g_hi);
    cudaGetSymbolAddress((void**)&ll1, g_ll1);
    cudaGetSymbolAddress((void**)&lh1, g_lh1);
    cudaGetSymbolAddress((void**)&hl1, g_hl1);
    cudaGetSymbolAddress((void**)&hh1, g_hh1);
    cudaGetSymbolAddress((void**)&ll2, g_ll2);
    cudaGetSymbolAddress((void**)&lh2, g_lh2);
    cudaGetSymbolAddress((void**)&hl2, g_hl2);
    cudaGetSymbolAddress((void**)&hh2, g_hh2);
    cudaGetSymbolAddress((void**)&b3,  g_b3);
    cudaGetSymbolAddress((void**)&wT,  g_wT);

    fc0_kernel<<<grd((long)PP * HW, 256), 256>>>(x, fc0_w, fc0_b, h);

    for (int layer = 0; layer < 4; layer++) {
        // ---------------- forward DWT (3 levels) ----------------
        // L1: 256x256 -> row -> 256x133 -> col -> 133x133 x4
        afb_row_k<<<dim3(N1, PP), 64>>>(h, lo, hi, N1, O1, 10, HW, N1);
        afb_col2<<<dim3(grd(O1,64), grd(O1,SEG), 2*PP), 64>>>(
            lo, hi, ll1, lh1, hl1, hh1, N1, O1, O1);
        // L2: 133x133 -> 133x72 -> 72x72 x4
        afb_row_k<<<dim3(O1, PP), 64>>>(ll1, lo, hi, O1, O2, 11, (long)O1*O1, O1);
        afb_col2<<<dim3(grd(O2,64), grd(O2,SEG), 2*PP), 64>>>(
            lo, hi, ll2, lh2, hl2, hh2, O1, O2, O2);
        // L3: 72x72 -> 72x41 -> 41x41 x4
        afb_row_k<<<dim3(O2, PP), 64>>>(ll2, lo, hi, O2, O3, 10, (long)O2*O2, O2);
        afb_col2<<<dim3(grd(O3,64), grd(O3,SEG), 2*PP), 64>>>(
            lo, hi, b3 + 0L*B3SZ, b3 + 1L*B3SZ, b3 + 2L*B3SZ, b3 + 3L*B3SZ,
            O2, O3, O3);

        // ---------------- coarsest-level channel mix ----------------
        transpose_w<<<dim3(grd(PIX3,32), grd(9216,32)), dim3(32,8)>>>(wc[layer], wT);
        mix_kernel<<<dim3(PIX3, 4), 384>>>(b3, wT, b3 + 4L*B3SZ);

        // ---------------- inverse DWT ----------------
        // L3: 41 -> 72
        sfb_col2<<<dim3(grd(O3,64), grd(36,USEG), 2*PP), 64>>>(
            b3 + 4L*B3SZ, b3 + 5L*B3SZ, b3 + 6L*B3SZ, b3 + 7L*B3SZ,
            lo, hi, O3, O3, 72,
            PIX3, O3, PIX3, O3, PIX3, O3, PIX3, O3);
        sfb_row_k<<<dim3(72, PP), 64>>>(lo, hi, ll2, O3, 72,
                                        72L*O3, O3, 72L*O3, O3);
        // L2: 72 -> 134
        sfb_col2<<<dim3(grd(O2,64), grd(67,USEG), 2*PP), 64>>>(
            ll2, lh2, hl2, hh2, lo, hi, O2, O2, 134,
            (long)O2*O2, O2, (long)O2*O2, O2, (long)O2*O2, O2, (long)O2*O2, O2);
        sfb_row_k<<<dim3(134, PP), 64>>>(lo, hi, h1, O2, 134,
                                         134L*O2, O2, 134L*O2, O2);
        // L1: 133 (crop of 134) -> 256
        sfb_col2<<<dim3(grd(O1,64), grd(128,USEG), 2*PP), 64>>>(
            h1, lh1, hl1, hh1, lo, hi, O1, O1, 256,
            134L*134, 134, (long)O1*O1, O1, (long)O1*O1, O1, (long)O1*O1, O1);
        sfb_row_k<<<dim3(256, PP), 64>>>(lo, hi, h1, O1, 256,
                                         256L*O1, O1, 256L*O1, O1);

        // ---------------- pointwise conv + add + gelu ----------------
        pw_kernel<<<2048, 256>>>(h, h1, cw + (size_t)layer * 2304,
                                 cb + (size_t)layer * 48, layer < 3 ? 1 : 0);
    }

    head_kernel<<<grd(8L * 255 * 255, 256), 256>>>(h, fc1_w, fc1_b, fc2_w, fc2_b, out);
}

// round 4
// speedup vs baseline: 2.7422x; 1.0098x over previous
#include <cuda_runtime.h>
#include <math.h>

#define BB 8
#define CC 48
#define PP (BB*CC)          // 384 planes
#define N1 256
#define O1 133
#define O2 72
#define O3 41
#define HW (N1*N1)          // 65536
#define PIX3 (O3*O3)        // 1681
#define B3SZ (PP*PIX3)      // 645504
#define SEG 12              // afb_col outputs per thread
#define USEG 8              // sfb_col output-pairs per thread

// coefficient literal lists -> local const arrays -> FFMA immediates after unroll
#define DLO_LIST { \
    -0.00107730108499558f, 0.004777257511010651f, 0.0005538422009938016f, \
    -0.031582039318031156f, 0.02752286553001629f, 0.09750160558707936f, \
    -0.12976686756709563f, -0.22626469396516913f, 0.3152503517092432f, \
    0.7511339080215775f, 0.4946238903983854f, 0.11154074335008017f }
#define DHI_LIST { \
    -0.11154074335008017f, 0.4946238903983854f, -0.7511339080215775f, \
    0.3152503517092432f, 0.22626469396516913f, -0.12976686756709563f, \
    -0.09750160558707936f, 0.02752286553001629f, 0.031582039318031156f, \
    0.0005538422009938016f, -0.004777257511010651f, -0.00107730108499558f }

// ------------------- scratch arena (static device memory) -------------------
__device__ float g_h  [PP*HW];
__device__ float g_h1 [PP*HW];      // also holds 134x134 IDWT intermediate
__device__ float g_lo [PP*N1*O1];
__device__ float g_hi [PP*N1*O1];
__device__ float g_ll1[PP*O1*O1];
__device__ float g_lh1[PP*O1*O1];
__device__ float g_hl1[PP*O1*O1];
__device__ float g_hh1[PP*O1*O1];
__device__ float g_ll2[PP*O2*O2];
__device__ float g_lh2[PP*O2*O2];
__device__ float g_hl2[PP*O2*O2];
__device__ float g_hh2[PP*O2*O2];
__device__ float g_b3 [8*B3SZ];     // slots: 0..3 raw ll,lh,hl,hh ; 4..7 mixed

// --------------------------- f32x2 packed helpers ---------------------------
__device__ __forceinline__ unsigned long long pack2(float x, float y) {
    unsigned long long r;
    asm("mov.b64 %0, {%1, %2};" : "=l"(r) : "f"(x), "f"(y));
    return r;
}
__device__ __forceinline__ void unpack2(unsigned long long v, float &x, float &y) {
    asm("mov.b64 {%0, %1}, %2;" : "=f"(x), "=f"(y) : "l"(v));
}
__device__ __forceinline__ unsigned long long ffma2(unsigned long long a,
                                                    unsigned long long b,
                                                    unsigned long long c) {
    unsigned long long d;
    asm("fma.rn.f32x2 %0, %1, %2, %3;" : "=l"(d) : "l"(a), "l"(b), "l"(c));
    return d;
}

__device__ __forceinline__ float gelu_f(float x) {
    return 0.5f * x * (1.0f + erff(x * 0.7071067811865475f));
}

// ------------------------------ fc0 + pad -----------------------------------
__global__ void fc0_kernel(const float* __restrict__ x,
                           const float* __restrict__ w,
                           const float* __restrict__ b,
                           float* __restrict__ out) {
    int idx = blockIdx.x * blockDim.x + threadIdx.x;
    if (idx >= PP * HW) return;
    int p  = idx & (HW - 1);
    int pc = idx >> 16;
    int ch = pc % CC, bb = pc / CC;
    int r = p >> 8, c = p & 255;
    float v = 0.f;
    if (r < 255 && c < 255) {
        const float* xp = x + (((size_t)bb * 255 + r) * 255 + c) * 4;
        v = b[ch];
        #pragma unroll
        for (int i = 0; i < 4; i++) v += xp[i] * w[i * CC + ch];
    }
    out[idx] = v;
}

// ------------------- analysis, row direction (smem-staged) -------------------
// grid (R, PP), block 64. paired outputs k=2t,2t+1 share a 14-float window.
__global__ void afb_row_k(const float* __restrict__ in, float* __restrict__ lo,
                          float* __restrict__ hi, int N, int O, int padR,
                          long in_ps, int in_rs) {
    __shared__ float s[280];
    const float dlo[12] = DLO_LIST;
    const float dhi[12] = DHI_LIST;
    int r = blockIdx.x, p = blockIdx.y;
    const float* row = in + (size_t)p * in_ps + (size_t)r * in_rs;
    int tid = threadIdx.x;
    int tot = N + 10 + padR;
    for (int i = tid; i < tot; i += 64) {
        int idx = i - 10;
        idx = (idx < 0)  ? -1 - idx : idx;
        idx = (idx >= N) ? 2 * N - 1 - idx : idx;
        s[i] = row[idx];
    }
    __syncthreads();
    size_t ob = ((size_t)p * gridDim.x + r) * O;
    int npairs = (O + 1) >> 1;
    for (int t = tid; t < npairs; t += 64) {
        float v[14];
        #pragma unroll
        for (int m = 0; m < 7; m++) {
            float2 pr = ((const float2*)s)[2 * t + m];
            v[2 * m] = pr.x; v[2 * m + 1] = pr.y;
        }
        float ale = 0.f, ahe = 0.f, alo = 0.f, aho = 0.f;
        #pragma unroll
        for (int j = 0; j < 12; j++) {
            ale += v[j]     * dlo[11 - j];
            ahe += v[j]     * dhi[11 - j];
            alo += v[j + 2] * dlo[11 - j];
            aho += v[j + 2] * dhi[11 - j];
        }
        int k = 2 * t;
        lo[ob + k] = ale;  hi[ob + k] = ahe;
        if (k + 1 < O) { lo[ob + k + 1] = alo; hi[ob + k + 1] = aho; }
    }
}

// ------------- analysis, col direction (sliding window, 2 inputs) ------------
__global__ void afb_col2(const float* __restrict__ inA, const float* __restrict__ inB,
                         float* __restrict__ loA, float* __restrict__ hiA,
                         float* __restrict__ loB, float* __restrict__ hiB,
                         int Nr, int Nc, int Or) {
    const float dlo[12] = DLO_LIST;
    const float dhi[12] = DHI_LIST;
    int c = blockIdx.x * 64 + threadIdx.x;
    if (c >= Nc) return;
    int z = blockIdx.z;
    const float* in = (z < PP) ? inA : inB;
    float* lo = (z < PP) ? loA : loB;
    float* hi = (z < PP) ? hiA : hiB;
    int p = (z < PP) ? z : z - PP;
    int k0 = blockIdx.y * SEG;
    const float* base = in + (size_t)p * Nr * Nc + c;
    float w[12];
    #pragma unroll
    for (int t = 0; t < 12; t++) {
        int i = 2 * k0 - 10 + t;
        i = (i < 0)   ? -1 - i : i;
        i = (i >= Nr) ? 2 * Nr - 1 - i : i;
        w[t] = base[(size_t)i * Nc];
    }
    size_t ob = ((size_t)p * Or + k0) * Nc + c;
    #pragma unroll
    for (int s = 0; s < SEG; s++) {
        int k = k0 + s;
        if (k < Or) {
            float a = 0.f, bv = 0.f;
            #pragma unroll
            for (int t = 0; t < 12; t++) {
                a  += w[t] * dlo[11 - t];
                bv += w[t] * dhi[11 - t];
            }
            lo[ob] = a;
            hi[ob] = bv;
        }
        ob += Nc;
        #pragma unroll
        for (int t = 0; t < 10; t++) w[t] = w[t + 2];
        int i2 = 2 * k + 2, i3 = 2 * k + 3;
        i2 = (i2 >= Nr) ? 2 * Nr - 1 - i2 : i2;
        i3 = (i3 >= Nr) ? 2 * Nr - 1 - i3 : i3;
        w[10] = base[(size_t)i2 * Nc];
        w[11] = base[(size_t)i3 * Nc];
    }
}

// ------------- synthesis, col direction (sliding window, 2 pairs) ------------
__global__ void sfb_col2(const float* __restrict__ loA, const float* __restrict__ hiA,
                         const float* __restrict__ loB, const float* __restrict__ hiB,
                         float* __restrict__ outA, float* __restrict__ outB,
                         int n, int Nc, int Or,
                         long loA_ps, int loA_rs, long hiA_ps, int hiA_rs,
                         long loB_ps, int loB_rs, long hiB_ps, int hiB_rs) {
    const float dlo[12] = DLO_LIST;
    const float dhi[12] = DHI_LIST;
    int c = blockIdx.x * 64 + threadIdx.x;
    if (c >= Nc) return;
    int z = blockIdx.z;
    int p = (z < PP) ? z : z - PP;
    const float* lp;
    const float* hp;
    float* out;
    long lo_rs, hi_rs;
    if (z < PP) {
        lp = loA + (size_t)p * loA_ps + c; hp = hiA + (size_t)p * hiA_ps + c;
        out = outA; lo_rs = loA_rs; hi_rs = hiA_rs;
    } else {
        lp = loB + (size_t)p * loB_ps + c; hp = hiB + (size_t)p * hiB_ps + c;
        out = outB; lo_rs = loB_rs; hi_rs = hiB_rs;
    }
    int u0 = blockIdx.y * USEG;
    float wl[6], wh[6];
    #pragma unroll
    for (int t = 0; t < 6; t++) {
        wl[t] = lp[(size_t)(u0 + t) * lo_rs];
        wh[t] = hp[(size_t)(u0 + t) * hi_rs];
    }
    size_t ob = ((size_t)p * Or + 2 * u0) * Nc + c;
    #pragma unroll
    for (int s = 0; s < USEG; s++) {
        int u = u0 + s;
        if (2 * u < Or) {
            float e = 0.f, o = 0.f;
            #pragma unroll
            for (int kk = 0; kk < 6; kk++) {
                e += wl[kk] * dlo[2 * kk + 1] + wh[kk] * dhi[2 * kk + 1];
                o += wl[kk] * dlo[2 * kk]     + wh[kk] * dhi[2 * kk];
            }
            out[ob] = e;
            out[ob + Nc] = o;
        }
        ob += 2 * (size_t)Nc;
        #pragma unroll
        for (int t = 0; t < 5; t++) { wl[t] = wl[t + 1]; wh[t] = wh[t + 1]; }
        int idx = u + 6;
        if (idx < n) {
            wl[5] = lp[(size_t)idx * lo_rs];
            wh[5] = hp[(size_t)idx * hi_rs];
        }
    }
}

// ------------------- synthesis, row direction (smem-staged) ------------------
__global__ void sfb_row_k(const float* __restrict__ lo, const float* __restrict__ hi,
                          float* __restrict__ out, int n, int Ow,
                          long lo_ps, int lo_rs, long hi_ps, int hi_rs) {
    __shared__ float sl[136], sh[136];
    const float dlo[12] = DLO_LIST;
    const float dhi[12] = DHI_LIST;
    int r = blockIdx.x, p = blockIdx.y;
    const float* lp = lo + (size_t)p * lo_ps + (size_t)r * lo_rs;
    const float* hp = hi + (size_t)p * hi_ps + (size_t)r * hi_rs;
    int tid = threadIdx.x;
    for (int i = tid; i < n; i += 64) { sl[i] = lp[i]; sh[i] = hp[i]; }
    __syncthreads();
    size_t ob = ((size_t)p * gridDim.x + r) * Ow;
    int np = Ow >> 1;
    for (int u = tid; u < np; u += 64) {
        float e = 0.f, o = 0.f;
        #pragma unroll
        for (int kk = 0; kk < 6; kk++) {
            float a = sl[u + kk], b = sh[u + kk];
            e += a * dlo[2 * kk + 1] + b * dhi[2 * kk + 1];
            o += a * dlo[2 * kk]     + b * dhi[2 * kk];
        }
        *(float2*)&out[ob + 2 * u] = make_float2(e, o);
    }
}

// --------------------- per-pixel 48x48 channel mix (41x41) ------------------
// 16-pixel tiles, direct coalesced weight reads (no transpose).
// grid (ceil(PIX3/16)=106, 4 bands), block 384. thread -> (b, o), 16 acc px.
__global__ void mix_kernel(const float* __restrict__ b3in, const float* __restrict__ w,
                           float* __restrict__ b3out) {
    __shared__ float ts[384 * 18];      // [plane][18] padded rows
    __shared__ float ws[4 * 48 * 18];   // [i-chunk 4][o 48][18]
    int px0 = blockIdx.x * 16;
    int band = blockIdx.y;
    int tid = threadIdx.x;
    // stage ts
    for (int e = tid; e < 384 * 16; e += 384) {
        int plane = e >> 4, px = e & 15;
        int gp = px0 + px;
        ts[plane * 18 + px] = (gp < PIX3)
            ? b3in[(size_t)band * B3SZ + (size_t)plane * PIX3 + gp] : 0.f;
    }
    int b = tid / 48, o = tid - b * 48;
    unsigned long long acc[8];
    #pragma unroll
    for (int m = 0; m < 8; m++) acc[m] = 0ull;
    const float* wband = w + (size_t)band * 2304 * PIX3;
    for (int ic = 0; ic < 12; ic++) {
        __syncthreads();
        // stage ws chunk: 4 x 48 x 16 = 3072 elems
        for (int e = tid; e < 3072; e += 384) {
            int ii = e / 768;
            int rem = e - ii * 768;
            int oo = rem >> 4, px = rem & 15;
            int gp = px0 + px;
            ws[(ii * 48 + oo) * 18 + px] = (gp < PIX3)
                ? wband[((size_t)(ic * 4 + ii) * 48 + oo) * PIX3 + gp] : 0.f;
        }
        __syncthreads();
        #pragma unroll
        for (int i = 0; i < 4; i++) {
            const unsigned long long* tr =
                (const unsigned long long*)(ts + (b * 48 + ic * 4 + i) * 18);
            const unsigned long long* wr =
                (const unsigned long long*)(ws + (i * 48 + o) * 18);
            #pragma unroll
            for (int m = 0; m < 8; m++) acc[m] = ffma2(tr[m], wr[m], acc[m]);
        }
    }
    size_t obase = (size_t)band * B3SZ + (size_t)(b * 48 + o) * PIX3 + px0;
    #pragma unroll
    for (int m = 0; m < 8; m++) {
        float x, y;
        unpack2(acc[m], x, y);
        int gp0 = px0 + 2 * m;
        if (gp0 < PIX3)     b3out[obase + 2 * m]     = x;
        if (gp0 + 1 < PIX3) b3out[obase + 2 * m + 1] = y;
    }
}

// ------------------ pointwise conv + residual add + gelu --------------------
__global__ void pw_kernel(float* __restrict__ h, const float* __restrict__ h1,
                          const float* __restrict__ cw, const float* __restrict__ cb,
                          int do_gelu) {
    __shared__ unsigned long long ws2[2304];
    __shared__ float bs[48];
    int tid = threadIdx.x;
    for (int j = tid; j < 2304; j += 256) {
        int o = j / 48, i = j - o * 48;
        float w = cw[j];
        ws2[i * 48 + o] = pack2(w, w);
    }
    if (tid < 48) bs[tid] = cb[tid];
    __syncthreads();
    int og = tid >> 6;
    int pq = tid & 63;
    int bx = blockIdx.x;
    int bb = bx >> 8;
    int p0 = ((bx & 255) << 8) + (pq << 2);
    size_t base = ((size_t)bb * CC) * HW + p0;
    unsigned long long acc[12][2];
    #pragma unroll
    for (int o = 0; o < 12; o++) {
        float b = bs[og * 12 + o];
        acc[o][0] = pack2(b, b);
        acc[o][1] = acc[o][0];
    }
    for (int i = 0; i < 48; i++) {
        ulonglong2 v = *(const ulonglong2*)(h + base + (size_t)i * HW);
        #pragma unroll
        for (int o = 0; o < 12; o++) {
            unsigned long long w2 = ws2[i * 48 + og * 12 + o];
            acc[o][0] = ffma2(v.x, w2, acc[o][0]);
            acc[o][1] = ffma2(v.y, w2, acc[o][1]);
        }
    }
    __syncthreads();
    #pragma unroll
    for (int o = 0; o < 12; o++) {
        int oc = og * 12 + o;
        float4 r = *(const float4*)(h1 + base + (size_t)oc * HW);
        float a, b, c, d;
        unpack2(acc[o][0], a, b);
        unpack2(acc[o][1], c, d);
        a += r.x; b += r.y; c += r.z; d += r.w;
        if (do_gelu) { a = gelu_f(a); b = gelu_f(b); c = gelu_f(c); d = gelu_f(d); }
        *(float4*)(h + base + (size_t)oc * HW) = make_float4(a, b, c, d);
    }
}

// -------------------------- fused fc1+gelu+fc2 head --------------------------
__global__ void head_kernel(const float* __restrict__ h, const float* __restrict__ w1,
                            const float* __restrict__ b1, const float* __restrict__ w2,
                            const float* __restrict__ b2, float* __restrict__ out) {
    __shared__ unsigned long long w1s[1536];
    __shared__ float b1s[64];
    __shared__ float w2s[64];
    int tid = threadIdx.x;
    const unsigned long long* w1u = (const unsigned long long*)w1;
    for (int j = tid; j < 1536; j += 256) w1s[j] = w1u[j];
    if (tid < 64) { b1s[tid] = b1[tid]; w2s[tid] = w2[tid]; }
    __syncthreads();
    int q = blockIdx.x * 256 + tid;
    if (q >= 8 * 255 * 255) return;
    int c = q % 255;
    int t2 = q / 255;
    int r = t2 % 255;
    int bb = t2 / 255;
    size_t base = ((size_t)bb * CC) * HW + (size_t)r * 256 + c;
    unsigned long long acc[32];
    #pragma unroll
    for (int j = 0; j < 32; j++) acc[j] = pack2(b1s[2 * j], b1s[2 * j + 1]);
    for (int i = 0; i < 48; i++) {
        float v = h[base + (size_t)i * HW];
        unsigned long long vv = pack2(v, v);
        #pragma unroll
        for (int j = 0; j < 32; j++) acc[j] = ffma2(vv, w1s[i * 32 + j], acc[j]);
    }
    float o = b2[0];
    #pragma unroll
    for (int j = 0; j < 32; j++) {
        float a, b;
        unpack2(acc[j], a, b);
        o += gelu_f(a) * w2s[2 * j] + gelu_f(b) * w2s[2 * j + 1];
    }
    out[q] = o;
}

// ---------------------------------- launch ----------------------------------
static inline int grd(long n, int bs) { return (int)((n + bs - 1) / bs); }

extern "C" void kernel_launch(void* const* d_in, const int* in_sizes, int n_in,
                              void* d_out, int out_size) {
    const float* x     = (const float*)d_in[0];
    const float* fc0_w = (const float*)d_in[1];
    const float* fc0_b = (const float*)d_in[2];
    const float* wc[4] = { (const float*)d_in[3], (const float*)d_in[4],
                           (const float*)d_in[5], (const float*)d_in[6] };
    const float* cw    = (const float*)d_in[7];
    const float* cb    = (const float*)d_in[8];
    const float* fc1_w = (const float*)d_in[9];
    const float* fc1_b = (const float*)d_in[10];
    const float* fc2_w = (const float*)d_in[11];
    const float* fc2_b = (const float*)d_in[12];
    float* out = (float*)d_out;

    float *h, *h1, *lo, *hi, *ll1, *lh1, *hl1, *hh1, *ll2, *lh2, *hl2, *hh2, *b3;
    cudaGetSymbolAddress((void**)&h,   g_h);
    cudaGetSymbolAddress((void**)&h1,  g_h1);
    cudaGetSymbolAddress((void**)&lo,  g_lo);
    cudaGetSymbolAddress((void**)&hi,  g_hi);
    cudaGetSymbolAddress((void**)&ll1, g_ll1);
    cudaGetSymbolAddress((void**)&lh1, g_lh1);
    cudaGetSymbolAddress((void**)&hl1, g_hl1);
    cudaGetSymbolAddress((void**)&hh1, g_hh1);
    cudaGetSymbolAddress((void**)&ll2, g_ll2);
    cudaGetSymbolAddress((void**)&lh2, g_lh2);
    cudaGetSymbolAddress((void**)&hl2, g_hl2);
    cudaGetSymbolAddress((void**)&hh2, g_hh2);
    cudaGetSymbolAddress((void**)&b3,  g_b3);

    fc0_kernel<<<grd((long)PP * HW, 256), 256>>>(x, fc0_w, fc0_b, h);

    for (int layer = 0; layer < 4; layer++) {
        // ---------------- forward DWT (3 levels) ----------------
        afb_row_k<<<dim3(N1, PP), 64>>>(h, lo, hi, N1, O1, 10, HW, N1);
        afb_col2<<<dim3(grd(O1,64), grd(O1,SEG), 2*PP), 64>>>(
            lo, hi, ll1, lh1, hl1, hh1, N1, O1, O1);
        afb_row_k<<<dim3(O1, PP), 64>>>(ll1, lo, hi, O1, O2, 11, (long)O1*O1, O1);
        afb_col2<<<dim3(grd(O2,64), grd(O2,SEG), 2*PP), 64>>>(
            lo, hi, ll2, lh2, hl2, hh2, O1, O2, O2);
        afb_row_k<<<dim3(O2, PP), 64>>>(ll2, lo, hi, O2, O3, 10, (long)O2*O2, O2);
        afb_col2<<<dim3(grd(O3,64), grd(O3,SEG), 2*PP), 64>>>(
            lo, hi, b3 + 0L*B3SZ, b3 + 1L*B3SZ, b3 + 2L*B3SZ, b3 + 3L*B3SZ,
            O2, O3, O3);

        // ---------------- coarsest-level channel mix ----------------
        mix_kernel<<<dim3(grd(PIX3,16), 4), 384>>>(b3, wc[layer], b3 + 4L*B3SZ);

        // ---------------- inverse DWT ----------------
        sfb_col2<<<dim3(grd(O3,64), grd(36,USEG), 2*PP), 64>>>(
            b3 + 4L*B3SZ, b3 + 5L*B3SZ, b3 + 6L*B3SZ, b3 + 7L*B3SZ,
            lo, hi, O3, O3, 72,
            PIX3, O3, PIX3, O3, PIX3, O3, PIX3, O3);
        sfb_row_k<<<dim3(72, PP), 64>>>(lo, hi, ll2, O3, 72,
                                        72L*O3, O3, 72L*O3, O3);
        sfb_col2<<<dim3(grd(O2,64), grd(67,USEG), 2*PP), 64>>>(
            ll2, lh2, hl2, hh2, lo, hi, O2, O2, 134,
            (long)O2*O2, O2, (long)O2*O2, O2, (long)O2*O2, O2, (long)O2*O2, O2);
        sfb_row_k<<<dim3(134, PP), 64>>>(lo, hi, h1, O2, 134,
                                         134L*O2, O2, 134L*O2, O2);
        sfb_col2<<<dim3(grd(O1,64), grd(128,USEG), 2*PP), 64>>>(
            h1, lh1, hl1, hh1, lo, hi, O1, O1, 256,
            134L*134, 134, (long)O1*O1, O1, (long)O1*O1, O1, (long)O1*O1, O1);
        sfb_row_k<<<dim3(256, PP), 64>>>(lo, hi, h1, O1, 256,
                                         256L*O1, O1, 256L*O1, O1);

        // ---------------- pointwise conv + add + gelu ----------------
        pw_kernel<<<2048, 256>>>(h, h1, cw + (size_t)layer * 2304,
                                 cb + (size_t)layer * 48, layer < 3 ? 1 : 0);
    }

    head_kernel<<<grd(8L * 255 * 255, 256), 256>>>(h, fc1_w, fc1_b, fc2_w, fc2_b, out);
}

// round 5
// speedup vs baseline: 2.7732x; 1.0113x over previous
#include <cuda_runtime.h>
#include <math.h>

#define BB 8
#define CC 48
#define PP (BB*CC)          // 384 planes
#define N1 256
#define O1 133
#define O2 72
#define O3 41
#define HW (N1*N1)          // 65536
#define PIX3 (O3*O3)        // 1681
#define B3SZ (PP*PIX3)      // 645504

// coefficient literal lists -> local const arrays -> FFMA immediates after unroll
#define DLO_LIST { \
    -0.00107730108499558f, 0.004777257511010651f, 0.0005538422009938016f, \
    -0.031582039318031156f, 0.02752286553001629f, 0.09750160558707936f, \
    -0.12976686756709563f, -0.22626469396516913f, 0.3152503517092432f, \
    0.7511339080215775f, 0.4946238903983854f, 0.11154074335008017f }
#define DHI_LIST { \
    -0.11154074335008017f, 0.4946238903983854f, -0.7511339080215775f, \
    0.3152503517092432f, 0.22626469396516913f, -0.12976686756709563f, \
    -0.09750160558707936f, 0.02752286553001629f, 0.031582039318031156f, \
    0.0005538422009938016f, -0.004777257511010651f, -0.00107730108499558f }

// ------------------- scratch arena (static device memory) -------------------
__device__ float g_h  [PP*HW];
__device__ float g_h1 [PP*HW];      // holds 134x134 IDWT intermediate (L2 out)
__device__ float g_h2 [PP*HW];      // L1 synthesis output (pre-pointwise)
__device__ float g_ll1[PP*O1*O1];
__device__ float g_lh1[PP*O1*O1];
__device__ float g_hl1[PP*O1*O1];
__device__ float g_hh1[PP*O1*O1];
__device__ float g_ll2[PP*O2*O2];   // analysis ll2; later reused for L3 synth out
__device__ float g_lh2[PP*O2*O2];
__device__ float g_hl2[PP*O2*O2];
__device__ float g_hh2[PP*O2*O2];
__device__ float g_b3 [8*B3SZ];     // slots: 0..3 raw ll,lh,hl,hh ; 4..7 mixed

// --------------------------- f32x2 packed helpers ---------------------------
__device__ __forceinline__ unsigned long long pack2(float x, float y) {
    unsigned long long r;
    asm("mov.b64 %0, {%1, %2};" : "=l"(r) : "f"(x), "f"(y));
    return r;
}
__device__ __forceinline__ void unpack2(unsigned long long v, float &x, float &y) {
    asm("mov.b64 {%0, %1}, %2;" : "=f"(x), "=f"(y) : "l"(v));
}
__device__ __forceinline__ unsigned long long ffma2(unsigned long long a,
                                                    unsigned long long b,
                                                    unsigned long long c) {
    unsigned long long d;
    asm("fma.rn.f32x2 %0, %1, %2, %3;" : "=l"(d) : "l"(a), "l"(b), "l"(c));
    return d;
}

__device__ __forceinline__ float gelu_f(float x) {
    return 0.5f * x * (1.0f + erff(x * 0.7071067811865475f));
}

__device__ __forceinline__ int reflect1(int i, int n) {
    i = (i < 0)  ? -1 - i : i;
    i = (i >= n) ? 2 * n - 1 - i : i;
    return i;
}

// ------------------------------ fc0 + pad -----------------------------------
__global__ void fc0_kernel(const float* __restrict__ x,
                           const float* __restrict__ w,
                           const float* __restrict__ b,
                           float* __restrict__ out) {
    int idx = blockIdx.x * blockDim.x + threadIdx.x;
    if (idx >= PP * HW) return;
    int p  = idx & (HW - 1);
    int pc = idx >> 16;
    int ch = pc % CC, bb = pc / CC;
    int r = p >> 8, c = p & 255;
    float v = 0.f;
    if (r < 255 && c < 255) {
        const float* xp = x + (((size_t)bb * 255 + r) * 255 + c) * 4;
        v = b[ch];
        #pragma unroll
        for (int i = 0; i < 4; i++) v += xp[i] * w[i * CC + ch];
    }
    out[idx] = v;
}

// ---------------------- fused 2D analysis (row then col) --------------------
// Block: one plane (blockIdx.y), one strip of K output rows (blockIdx.x).
// Stages padded input rows chunk-wise, row-transforms into sLo/sHi (smem),
// then col-transforms to the 4 bands.
template<int NR, int NC, int OR, int OC, int PADR, int K, int CH>
__global__ void __launch_bounds__(256) afb2d(
    const float* __restrict__ in, long in_ps, int in_rs,
    float* __restrict__ ll, float* __restrict__ lh,
    float* __restrict__ hl, float* __restrict__ hh)
{
    constexpr int PW    = NC + 10 + PADR;      // padded row width
    constexpr int PWP   = (PW + 3) & ~1;       // +2 slack, even pitch
    constexpr int ROWS  = 2 * K + 11;          // intermediate rows needed
    constexpr int PITCH = (OC + 1) & ~1;       // even pitch for float2 col reads
    constexpr int NPAIR = (OC + 1) / 2;
    constexpr long OPS  = (long)OR * OC;
    __shared__ float sIn[CH * PWP];
    __shared__ float sLo[ROWS * PITCH];
    __shared__ float sHi[ROWS * PITCH];
    const float dlo[12] = DLO_LIST;
    const float dhi[12] = DHI_LIST;

    int p   = blockIdx.y;
    int k0  = blockIdx.x * K;
    int rbase = 2 * k0 - 10;
    int tid = threadIdx.x;
    const float* ip = in + (size_t)p * in_ps;

    for (int c0 = 0; c0 < ROWS; c0 += CH) {
        __syncthreads();
        // stage CH padded rows (row+col reflection applied once here)
        for (int e = tid; e < CH * PW; e += 256) {
            int j = e / PW, c = e - j * PW;
            int rr = reflect1(rbase + c0 + j, NR);
            int cc = reflect1(c - 10, NC);
            sIn[j * PWP + c] = ip[(size_t)rr * in_rs + cc];
        }
        __syncthreads();
        // row transform: paired outputs 2t, 2t+1 share a 14-float window
        for (int e = tid; e < CH * NPAIR; e += 256) {
            int j = e / NPAIR, t = e - j * NPAIR;
            int row = c0 + j;
            if (row < ROWS) {
                float v[14];
                const float2* sp = (const float2*)(sIn + j * PWP + 4 * t);
                #pragma unroll
                for (int m = 0; m < 7; m++) {
                    float2 q = sp[m];
                    v[2*m] = q.x; v[2*m+1] = q.y;
                }
                float ale = 0.f, ahe = 0.f, alo = 0.f, aho = 0.f;
                #pragma unroll
                for (int jj = 0; jj < 12; jj++) {
                    ale += v[jj]     * dlo[11 - jj];
                    ahe += v[jj]     * dhi[11 - jj];
                    alo += v[jj + 2] * dlo[11 - jj];
                    aho += v[jj + 2] * dhi[11 - jj];
                }
                sLo[row * PITCH + 2*t]     = ale;
                sHi[row * PITCH + 2*t]     = ahe;
                sLo[row * PITCH + 2*t + 1] = alo;   // padded slot if 2t+1==OC
                sHi[row * PITCH + 2*t + 1] = aho;
            }
        }
    }
    __syncthreads();
    // col transform, 2 columns per thread-item (float2 smem reads)
    for (int e = tid; e < K * NPAIR; e += 256) {
        int k = e / NPAIR, cp = e - k * NPAIR;
        int kg = k0 + k;
        if (kg < OR) {
            int c = 2 * cp;
            float a0x=0,a0y=0,a1x=0,a1y=0,a2x=0,a2y=0,a3x=0,a3y=0;
            #pragma unroll
            for (int t = 0; t < 12; t++) {
                float2 a = *(const float2*)&sLo[(2*k + t) * PITCH + c];
                float2 b = *(const float2*)&sHi[(2*k + t) * PITCH + c];
                a0x += a.x * dlo[11-t]; a0y += a.y * dlo[11-t];
                a1x += a.x * dhi[11-t]; a1y += a.y * dhi[11-t];
                a2x += b.x * dlo[11-t]; a2y += b.y * dlo[11-t];
                a3x += b.x * dhi[11-t]; a3y += b.y * dhi[11-t];
            }
            size_t o = (size_t)p * OPS + (size_t)kg * OC + c;
            ll[o] = a0x; lh[o] = a1x; hl[o] = a2x; hh[o] = a3x;
            if (c + 1 < OC) {
                ll[o+1] = a0y; lh[o+1] = a1y; hl[o+1] = a2y; hh[o+1] = a3y;
            }
        }
    }
}

// ---------------------- fused 2D synthesis (col then row) -------------------
// Inputs: 4 bands NIN x M (ll may have its own strides: L1 reads 134-pitch h1).
// Output plane: W2 x W where W2 = 2*NIN-10, W = 2*M-10.
template<int NIN, int M, int KO>
__global__ void __launch_bounds__(256) sfb2d(
    const float* __restrict__ bll, long ll_ps, int ll_rs,
    const float* __restrict__ blh, const float* __restrict__ bhl,
    const float* __restrict__ bhh, long b_ps,
    float* __restrict__ out)
{
    constexpr int W   = 2 * M - 10;
    constexpr int W2  = 2 * NIN - 10;
    constexpr int RIN = KO / 2 + 6;
    constexpr int MP  = (M + 1) & ~1;
    constexpr int CP  = (M + 1) / 2;
    constexpr int UP  = M - 5;
    __shared__ float s0[RIN*MP], s1[RIN*MP], s2[RIN*MP], s3[RIN*MP];
    __shared__ float sl[KO*MP], sh[KO*MP];
    const float dlo[12] = DLO_LIST;
    const float dhi[12] = DHI_LIST;

    int p  = blockIdx.y;
    int j0 = blockIdx.x * KO;     // KO even
    int r0 = j0 >> 1;
    int tid = threadIdx.x;
    const float* pll = bll + (size_t)p * ll_ps;
    const float* plh = blh + (size_t)p * b_ps;
    const float* phl = bhl + (size_t)p * b_ps;
    const float* phh = bhh + (size_t)p * b_ps;

    // stage band strips (clamp rows past the end; clamped rows never used)
    for (int e = tid; e < RIN * M; e += 256) {
        int r = e / M, c = e - r * M;
        int rr = r0 + r; rr = (rr > NIN - 1) ? NIN - 1 : rr;
        int se = r * MP + c;
        s0[se] = pll[(size_t)rr * ll_rs + c];
        s1[se] = plh[(size_t)rr * M + c];
        s2[se] = phl[(size_t)rr * M + c];
        s3[se] = phh[(size_t)rr * M + c];
    }
    __syncthreads();
    // column synthesis: each item makes output rows (2uj, 2uj+1) for 2 columns
    for (int e = tid; e < (KO/2) * CP; e += 256) {
        int uj = e / CP, cp = e - uj * CP;
        int c = 2 * cp;
        float elx=0,ely=0,olx=0,oly=0,ehx=0,ehy=0,ohx=0,ohy=0;
        #pragma unroll
        for (int kk = 0; kk < 6; kk++) {
            int sb = (uj + kk) * MP + c;
            float2 a  = *(const float2*)&s0[sb];
            float2 b  = *(const float2*)&s1[sb];
            float2 g  = *(const float2*)&s2[sb];
            float2 hq = *(const float2*)&s3[sb];
            float ce = dlo[2*kk+1], co = dlo[2*kk];
            float de = dhi[2*kk+1], dq = dhi[2*kk];
            elx += a.x*ce + b.x*de;   ely += a.y*ce + b.y*de;
            olx += a.x*co + b.x*dq;   oly += a.y*co + b.y*dq;
            ehx += g.x*ce + hq.x*de;  ehy += g.y*ce + hq.y*de;
            ohx += g.x*co + hq.x*dq;  ohy += g.y*co + hq.y*dq;
        }
        int sb0 = (2*uj) * MP + c, sb1 = (2*uj + 1) * MP + c;
        sl[sb0] = elx; sl[sb1] = olx; sh[sb0] = ehx; sh[sb1] = ohx;
        if (c + 1 < M) {
            sl[sb0+1] = ely; sl[sb1+1] = oly; sh[sb0+1] = ehy; sh[sb1+1] = ohy;
        }
    }
    __syncthreads();
    // row synthesis: output col pair (2u, 2u+1) per item, float2 store
    for (int e = tid; e < KO * UP; e += 256) {
        int j = e / UP, u = e - j * UP;
        int jg = j0 + j;
        if (jg < W2) {
            float ev = 0.f, od = 0.f;
            #pragma unroll
            for (int kk = 0; kk < 6; kk++) {
                float a = sl[j * MP + u + kk], b = sh[j * MP + u + kk];
                ev += a * dlo[2*kk+1] + b * dhi[2*kk+1];
                od += a * dlo[2*kk]   + b * dhi[2*kk];
            }
            *(float2*)&out[((size_t)p * W2 + jg) * W + 2*u] = make_float2(ev, od);
        }
    }
}

// --------------------- per-pixel 48x48 channel mix (41x41) ------------------
__global__ void mix_kernel(const float* __restrict__ b3in, const float* __restrict__ w,
                           float* __restrict__ b3out) {
    __shared__ float ts[384 * 18];
    __shared__ float ws[4 * 48 * 18];
    int px0 = blockIdx.x * 16;
    int band = blockIdx.y;
    int tid = threadIdx.x;
    for (int e = tid; e < 384 * 16; e += 384) {
        int plane = e >> 4, px = e & 15;
        int gp = px0 + px;
        ts[plane * 18 + px] = (gp < PIX3)
            ? b3in[(size_t)band * B3SZ + (size_t)plane * PIX3 + gp] : 0.f;
    }
    int b = tid / 48, o = tid - b * 48;
    unsigned long long acc[8];
    #pragma unroll
    for (int m = 0; m < 8; m++) acc[m] = 0ull;
    const float* wband = w + (size_t)band * 2304 * PIX3;
    for (int ic = 0; ic < 12; ic++) {
        __syncthreads();
        for (int e = tid; e < 3072; e += 384) {
            int ii = e / 768;
            int rem = e - ii * 768;
            int oo = rem >> 4, px = rem & 15;
            int gp = px0 + px;
            ws[(ii * 48 + oo) * 18 + px] = (gp < PIX3)
                ? wband[((size_t)(ic * 4 + ii) * 48 + oo) * PIX3 + gp] : 0.f;
        }
        __syncthreads();
        #pragma unroll
        for (int i = 0; i < 4; i++) {
            const unsigned long long* tr =
                (const unsigned long long*)(ts + (b * 48 + ic * 4 + i) * 18);
            const unsigned long long* wr =
                (const unsigned long long*)(ws + (i * 48 + o) * 18);
            #pragma unroll
            for (int m = 0; m < 8; m++) acc[m] = ffma2(tr[m], wr[m], acc[m]);
        }
    }
    size_t obase = (size_t)band * B3SZ + (size_t)(b * 48 + o) * PIX3 + px0;
    #pragma unroll
    for (int m = 0; m < 8; m++) {
        float x, y;
        unpack2(acc[m], x, y);
        int gp0 = px0 + 2 * m;
        if (gp0 < PIX3)     b3out[obase + 2 * m]     = x;
        if (gp0 + 1 < PIX3) b3out[obase + 2 * m + 1] = y;
    }
}

// ------------------ pointwise conv + residual add + gelu --------------------
__global__ void pw_kernel(float* __restrict__ h, const float* __restrict__ h2,
                          const float* __restrict__ cw, const float* __restrict__ cb,
                          int do_gelu) {
    __shared__ unsigned long long ws2[2304];
    __shared__ float bs[48];
    int tid = threadIdx.x;
    for (int j = tid; j < 2304; j += 256) {
        int o = j / 48, i = j - o * 48;
        float w = cw[j];
        ws2[i * 48 + o] = pack2(w, w);
    }
    if (tid < 48) bs[tid] = cb[tid];
    __syncthreads();
    int og = tid >> 6;
    int pq = tid & 63;
    int bx = blockIdx.x;
    int bb = bx >> 8;
    int p0 = ((bx & 255) << 8) + (pq << 2);
    size_t base = ((size_t)bb * CC) * HW + p0;
    unsigned long long acc[12][2];
    #pragma unroll
    for (int o = 0; o < 12; o++) {
        float b = bs[og * 12 + o];
        acc[o][0] = pack2(b, b);
        acc[o][1] = acc[o][0];
    }
    for (int i = 0; i < 48; i++) {
        ulonglong2 v = *(const ulonglong2*)(h + base + (size_t)i * HW);
        #pragma unroll
        for (int o = 0; o < 12; o++) {
            unsigned long long w2 = ws2[i * 48 + og * 12 + o];
            acc[o][0] = ffma2(v.x, w2, acc[o][0]);
            acc[o][1] = ffma2(v.y, w2, acc[o][1]);
        }
    }
    __syncthreads();
    #pragma unroll
    for (int o = 0; o < 12; o++) {
        int oc = og * 12 + o;
        float4 r = *(const float4*)(h2 + base + (size_t)oc * HW);
        float a, b, c, d;
        unpack2(acc[o][0], a, b);
        unpack2(acc[o][1], c, d);
        a += r.x; b += r.y; c += r.z; d += r.w;
        if (do_gelu) { a = gelu_f(a); b = gelu_f(b); c = gelu_f(c); d = gelu_f(d); }
        *(float4*)(h + base + (size_t)oc * HW) = make_float4(a, b, c, d);
    }
}

// -------------------------- fused fc1+gelu+fc2 head --------------------------
__global__ void head_kernel(const float* __restrict__ h, const float* __restrict__ w1,
                            const float* __restrict__ b1, const float* __restrict__ w2,
                            const float* __restrict__ b2, float* __restrict__ out) {
    __shared__ unsigned long long w1s[1536];
    __shared__ float b1s[64];
    __shared__ float w2s[64];
    int tid = threadIdx.x;
    const unsigned long long* w1u = (const unsigned long long*)w1;
    for (int j = tid; j < 1536; j += 256) w1s[j] = w1u[j];
    if (tid < 64) { b1s[tid] = b1[tid]; w2s[tid] = w2[tid]; }
    __syncthreads();
    int q = blockIdx.x * 256 + tid;
    if (q >= 8 * 255 * 255) return;
    int c = q % 255;
    int t2 = q / 255;
    int r = t2 % 255;
    int bb = t2 / 255;
    size_t base = ((size_t)bb * CC) * HW + (size_t)r * 256 + c;
    unsigned long long acc[32];
    #pragma unroll
    for (int j = 0; j < 32; j++) acc[j] = pack2(b1s[2 * j], b1s[2 * j + 1]);
    for (int i = 0; i < 48; i++) {
        float v = h[base + (size_t)i * HW];
        unsigned long long vv = pack2(v, v);
        #pragma unroll
        for (int j = 0; j < 32; j++) acc[j] = ffma2(vv, w1s[i * 32 + j], acc[j]);
    }
    float o = b2[0];
    #pragma unroll
    for (int j = 0; j < 32; j++) {
        float a, b;
        unpack2(acc[j], a, b);
        o += gelu_f(a) * w2s[2 * j] + gelu_f(b) * w2s[2 * j + 1];
    }
    out[q] = o;
}

// ---------------------------------- launch ----------------------------------
static inline int grd(long n, int bs) { return (int)((n + bs - 1) / bs); }

extern "C" void kernel_launch(void* const* d_in, const int* in_sizes, int n_in,
                              void* d_out, int out_size) {
    const float* x     = (const float*)d_in[0];
    const float* fc0_w = (const float*)d_in[1];
    const float* fc0_b = (const float*)d_in[2];
    const float* wc[4] = { (const float*)d_in[3], (const float*)d_in[4],
                           (const float*)d_in[5], (const float*)d_in[6] };
    const float* cw    = (const float*)d_in[7];
    const float* cb    = (const float*)d_in[8];
    const float* fc1_w = (const float*)d_in[9];
    const float* fc1_b = (const float*)d_in[10];
    const float* fc2_w = (const float*)d_in[11];
    const float* fc2_b = (const float*)d_in[12];
    float* out = (float*)d_out;

    float *h, *h1, *h2, *ll1, *lh1, *hl1, *hh1, *ll2, *lh2, *hl2, *hh2, *b3;
    cudaGetSymbolAddress((void**)&h,   g_h);
    cudaGetSymbolAddress((void**)&h1,  g_h1);
    cudaGetSymbolAddress((void**)&h2,  g_h2);
    cudaGetSymbolAddress((void**)&ll1, g_ll1);
    cudaGetSymbolAddress((void**)&lh1, g_lh1);
    cudaGetSymbolAddress((void**)&hl1, g_hl1);
    cudaGetSymbolAddress((void**)&hh1, g_hh1);
    cudaGetSymbolAddress((void**)&ll2, g_ll2);
    cudaGetSymbolAddress((void**)&lh2, g_lh2);
    cudaGetSymbolAddress((void**)&hl2, g_hl2);
    cudaGetSymbolAddress((void**)&hh2, g_hh2);
    cudaGetSymbolAddress((void**)&b3,  g_b3);

    fc0_kernel<<<grd((long)PP * HW, 256), 256>>>(x, fc0_w, fc0_b, h);

    for (int layer = 0; layer < 4; layer++) {
        // ---------------- forward DWT (3 fused levels) ----------------
        afb2d<256,256,133,133,10,13,4><<<dim3(11, PP), 256>>>(
            h, (long)HW, 256, ll1, lh1, hl1, hh1);
        afb2d<133,133,72,72,11,12,4><<<dim3(6, PP), 256>>>(
            ll1, 133L*133, 133, ll2, lh2, hl2, hh2);
        afb2d<72,72,41,41,10,14,4><<<dim3(3, PP), 256>>>(
            ll2, 72L*72, 72,
            b3 + 0L*B3SZ, b3 + 1L*B3SZ, b3 + 2L*B3SZ, b3 + 3L*B3SZ);

        // ---------------- coarsest-level channel mix ----------------
        mix_kernel<<<dim3(grd(PIX3,16), 4), 384>>>(b3, wc[layer], b3 + 4L*B3SZ);

        // ---------------- inverse DWT (3 fused levels) ----------------
        sfb2d<41,41,24><<<dim3(3, PP), 256>>>(
            b3 + 4L*B3SZ, (long)PIX3, 41,
            b3 + 5L*B3SZ, b3 + 6L*B3SZ, b3 + 7L*B3SZ, (long)PIX3, ll2);
        sfb2d<72,72,24><<<dim3(6, PP), 256>>>(
            ll2, 72L*72, 72, lh2, hl2, hh2, 72L*72, h1);
        sfb2d<133,133,16><<<dim3(16, PP), 256>>>(
            h1, 134L*134, 134, lh1, hl1, hh1, 133L*133, h2);

        // ---------------- pointwise conv + add + gelu ----------------
        pw_kernel<<<2048, 256>>>(h, h2, cw + (size_t)layer * 2304,
                                 cb + (size_t)layer * 48, layer < 3 ? 1 : 0);
    }

    head_kernel<<<grd(8L * 255 * 255, 256), 256>>>(h, fc1_w, fc1_b, fc2_w, fc2_b, out);
}

// round 6
// speedup vs baseline: 2.9290x; 1.0562x over previous
#include <cuda_runtime.h>
#include <math.h>

#define BB 8
#define CC 48
#define PP (BB*CC)          // 384 planes
#define N1 256
#define O1 133
#define O2 72
#define O3 41
#define HW (N1*N1)          // 65536
#define PIX3 (O3*O3)        // 1681
#define B3SZ (PP*PIX3)      // 645504

#define DLO_LIST { \
    -0.00107730108499558f, 0.004777257511010651f, 0.0005538422009938016f, \
    -0.031582039318031156f, 0.02752286553001629f, 0.09750160558707936f, \
    -0.12976686756709563f, -0.22626469396516913f, 0.3152503517092432f, \
    0.7511339080215775f, 0.4946238903983854f, 0.11154074335008017f }
#define DHI_LIST { \
    -0.11154074335008017f, 0.4946238903983854f, -0.7511339080215775f, \
    0.3152503517092432f, 0.22626469396516913f, -0.12976686756709563f, \
    -0.09750160558707936f, 0.02752286553001629f, 0.031582039318031156f, \
    0.0005538422009938016f, -0.004777257511010651f, -0.00107730108499558f }

// ------------------- scratch arena (static device memory) -------------------
__device__ float g_h  [PP*HW];
__device__ float g_h1 [PP*HW];      // 134x134 IDWT intermediate (L2 out)
__device__ float g_h2 [PP*HW];      // L1 synthesis output (pre-pointwise)
__device__ float g_ll1[PP*O1*O1];
__device__ float g_lh1[PP*O1*O1];
__device__ float g_hl1[PP*O1*O1];
__device__ float g_hh1[PP*O1*O1];
__device__ float g_ll2[PP*O2*O2];
__device__ float g_lh2[PP*O2*O2];
__device__ float g_hl2[PP*O2*O2];
__device__ float g_hh2[PP*O2*O2];
__device__ float g_b3 [8*B3SZ];

// --------------------------- f32x2 packed helpers ---------------------------
__device__ __forceinline__ unsigned long long pack2(float x, float y) {
    unsigned long long r;
    asm("mov.b64 %0, {%1, %2};" : "=l"(r) : "f"(x), "f"(y));
    return r;
}
__device__ __forceinline__ void unpack2(unsigned long long v, float &x, float &y) {
    asm("mov.b64 {%0, %1}, %2;" : "=f"(x), "=f"(y) : "l"(v));
}
__device__ __forceinline__ unsigned long long ffma2(unsigned long long a,
                                                    unsigned long long b,
                                                    unsigned long long c) {
    unsigned long long d;
    asm("fma.rn.f32x2 %0, %1, %2, %3;" : "=l"(d) : "l"(a), "l"(b), "l"(c));
    return d;
}

__device__ __forceinline__ float gelu_f(float x) {
    return 0.5f * x * (1.0f + erff(x * 0.7071067811865475f));
}

__device__ __forceinline__ int reflect1(int i, int n) {
    i = (i < 0)  ? -1 - i : i;
    i = (i >= n) ? 2 * n - 1 - i : i;
    return i;
}

// ------------------------------ fc0 + pad -----------------------------------
__global__ void fc0_kernel(const float* __restrict__ x,
                           const float* __restrict__ w,
                           const float* __restrict__ b,
                           float* __restrict__ out) {
    int idx = blockIdx.x * blockDim.x + threadIdx.x;
    if (idx >= PP * HW) return;
    int p  = idx & (HW - 1);
    int pc = idx >> 16;
    int ch = pc % CC, bb = pc / CC;
    int r = p >> 8, c = p & 255;
    float v = 0.f;
    if (r < 255 && c < 255) {
        const float* xp = x + (((size_t)bb * 255 + r) * 255 + c) * 4;
        v = b[ch];
        #pragma unroll
        for (int i = 0; i < 4; i++) v += xp[i] * w[i * CC + ch];
    }
    out[idx] = v;
}

// ---------------------- fused 2D analysis (row then col) --------------------
template<int NR, int NC, int OR, int OC, int PADR, int K, int CH, int THREADS>
__global__ void __launch_bounds__(THREADS) afb2d(
    const float* __restrict__ in, long in_ps, int in_rs,
    float* __restrict__ ll, float* __restrict__ lh,
    float* __restrict__ hl, float* __restrict__ hh)
{
    constexpr int PW    = NC + 10 + PADR;
    constexpr int PWP   = (PW + 3) & ~1;
    constexpr int ROWS  = 2 * K + 11;
    constexpr int PITCH = (OC + 1) & ~1;
    constexpr int NPAIR = (OC + 1) / 2;
    constexpr long OPS  = (long)OR * OC;
    extern __shared__ float smem[];
    float* sIn = smem;                       // CH * PWP
    float* sLo = smem + CH * PWP;            // ROWS * PITCH
    float* sHi = sLo + ROWS * PITCH;         // ROWS * PITCH
    const float dlo[12] = DLO_LIST;
    const float dhi[12] = DHI_LIST;

    int p   = blockIdx.y;
    int k0  = blockIdx.x * K;
    int rbase = 2 * k0 - 10;
    int tid = threadIdx.x;
    const float* ip = in + (size_t)p * in_ps;

    for (int c0 = 0; c0 < ROWS; c0 += CH) {
        __syncthreads();
        for (int e = tid; e < CH * PW; e += THREADS) {
            int j = e / PW, c = e - j * PW;
            int rr = reflect1(rbase + c0 + j, NR);
            int cc = reflect1(c - 10, NC);
            sIn[j * PWP + c] = ip[(size_t)rr * in_rs + cc];
        }
        __syncthreads();
        for (int e = tid; e < CH * NPAIR; e += THREADS) {
            int j = e / NPAIR, t = e - j * NPAIR;
            int row = c0 + j;
            if (row < ROWS) {
                float v[14];
                const float2* sp = (const float2*)(sIn + j * PWP + 4 * t);
                #pragma unroll
                for (int m = 0; m < 7; m++) {
                    float2 q = sp[m];
                    v[2*m] = q.x; v[2*m+1] = q.y;
                }
                float ale = 0.f, ahe = 0.f, alo = 0.f, aho = 0.f;
                #pragma unroll
                for (int jj = 0; jj < 12; jj++) {
                    ale += v[jj]     * dlo[11 - jj];
                    ahe += v[jj]     * dhi[11 - jj];
                    alo += v[jj + 2] * dlo[11 - jj];
                    aho += v[jj + 2] * dhi[11 - jj];
                }
                sLo[row * PITCH + 2*t]     = ale;
                sHi[row * PITCH + 2*t]     = ahe;
                sLo[row * PITCH + 2*t + 1] = alo;
                sHi[row * PITCH + 2*t + 1] = aho;
            }
        }
    }
    __syncthreads();
    for (int e = tid; e < K * NPAIR; e += THREADS) {
        int k = e / NPAIR, cp = e - k * NPAIR;
        int kg = k0 + k;
        if (kg < OR) {
            int c = 2 * cp;
            float a0x=0,a0y=0,a1x=0,a1y=0,a2x=0,a2y=0,a3x=0,a3y=0;
            #pragma unroll
            for (int t = 0; t < 12; t++) {
                float2 a = *(const float2*)&sLo[(2*k + t) * PITCH + c];
                float2 b = *(const float2*)&sHi[(2*k + t) * PITCH + c];
                a0x += a.x * dlo[11-t]; a0y += a.y * dlo[11-t];
                a1x += a.x * dhi[11-t]; a1y += a.y * dhi[11-t];
                a2x += b.x * dlo[11-t]; a2y += b.y * dlo[11-t];
                a3x += b.x * dhi[11-t]; a3y += b.y * dhi[11-t];
            }
            size_t o = (size_t)p * OPS + (size_t)kg * OC + c;
            ll[o] = a0x; lh[o] = a1x; hl[o] = a2x; hh[o] = a3x;
            if (c + 1 < OC) {
                ll[o+1] = a0y; lh[o+1] = a1y; hl[o+1] = a2y; hh[o+1] = a3y;
            }
        }
    }
}

// ---------------------- fused 2D synthesis (col then row) -------------------
template<int NIN, int M, int KO, int THREADS>
__global__ void __launch_bounds__(THREADS) sfb2d(
    const float* __restrict__ bll, long ll_ps, int ll_rs,
    const float* __restrict__ blh, const float* __restrict__ bhl,
    const float* __restrict__ bhh, long b_ps,
    float* __restrict__ out)
{
    constexpr int W   = 2 * M - 10;
    constexpr int W2  = 2 * NIN - 10;
    constexpr int RIN = KO / 2 + 6;
    constexpr int MP  = (M + 1) & ~1;
    constexpr int CP  = (M + 1) / 2;
    constexpr int UP  = M - 5;
    extern __shared__ float smem[];
    float* s0 = smem;                  // RIN*MP each
    float* s1 = s0 + RIN * MP;
    float* s2 = s1 + RIN * MP;
    float* s3 = s2 + RIN * MP;
    float* sl = s3 + RIN * MP;         // KO*MP each
    float* sh = sl + KO * MP;
    const float dlo[12] = DLO_LIST;
    const float dhi[12] = DHI_LIST;

    int p  = blockIdx.y;
    int j0 = blockIdx.x * KO;
    int r0 = j0 >> 1;
    int tid = threadIdx.x;
    const float* pll = bll + (size_t)p * ll_ps;
    const float* plh = blh + (size_t)p * b_ps;
    const float* phl = bhl + (size_t)p * b_ps;
    const float* phh = bhh + (size_t)p * b_ps;

    for (int e = tid; e < RIN * M; e += THREADS) {
        int r = e / M, c = e - r * M;
        int rr = r0 + r; rr = (rr > NIN - 1) ? NIN - 1 : rr;
        int se = r * MP + c;
        s0[se] = pll[(size_t)rr * ll_rs + c];
        s1[se] = plh[(size_t)rr * M + c];
        s2[se] = phl[(size_t)rr * M + c];
        s3[se] = phh[(size_t)rr * M + c];
    }
    __syncthreads();
    for (int e = tid; e < (KO/2) * CP; e += THREADS) {
        int uj = e / CP, cp = e - uj * CP;
        int c = 2 * cp;
        float elx=0,ely=0,olx=0,oly=0,ehx=0,ehy=0,ohx=0,ohy=0;
        #pragma unroll
        for (int kk = 0; kk < 6; kk++) {
            int sb = (uj + kk) * MP + c;
            float2 a  = *(const float2*)&s0[sb];
            float2 b  = *(const float2*)&s1[sb];
            float2 g  = *(const float2*)&s2[sb];
            float2 hq = *(const float2*)&s3[sb];
            float ce = dlo[2*kk+1], co = dlo[2*kk];
            float de = dhi[2*kk+1], dq = dhi[2*kk];
            elx += a.x*ce + b.x*de;   ely += a.y*ce + b.y*de;
            olx += a.x*co + b.x*dq;   oly += a.y*co + b.y*dq;
            ehx += g.x*ce + hq.x*de;  ehy += g.y*ce + hq.y*de;
            ohx += g.x*co + hq.x*dq;  ohy += g.y*co + hq.y*dq;
        }
        int sb0 = (2*uj) * MP + c, sb1 = (2*uj + 1) * MP + c;
        sl[sb0] = elx; sl[sb1] = olx; sh[sb0] = ehx; sh[sb1] = ohx;
        if (c + 1 < M) {
            sl[sb0+1] = ely; sl[sb1+1] = oly; sh[sb0+1] = ehy; sh[sb1+1] = ohy;
        }
    }
    __syncthreads();
    for (int e = tid; e < KO * UP; e += THREADS) {
        int j = e / UP, u = e - j * UP;
        int jg = j0 + j;
        if (jg < W2) {
            float ev = 0.f, od = 0.f;
            #pragma unroll
            for (int kk = 0; kk < 6; kk++) {
                float a = sl[j * MP + u + kk], b = sh[j * MP + u + kk];
                ev += a * dlo[2*kk+1] + b * dhi[2*kk+1];
                od += a * dlo[2*kk]   + b * dhi[2*kk];
            }
            *(float2*)&out[((size_t)p * W2 + jg) * W + 2*u] = make_float2(ev, od);
        }
    }
}

// --------------------- per-pixel 48x48 channel mix (41x41) ------------------
__global__ void mix_kernel(const float* __restrict__ b3in, const float* __restrict__ w,
                           float* __restrict__ b3out) {
    __shared__ float ts[384 * 18];
    __shared__ float ws[4 * 48 * 18];
    int px0 = blockIdx.x * 16;
    int band = blockIdx.y;
    int tid = threadIdx.x;
    for (int e = tid; e < 384 * 16; e += 384) {
        int plane = e >> 4, px = e & 15;
        int gp = px0 + px;
        ts[plane * 18 + px] = (gp < PIX3)
            ? b3in[(size_t)band * B3SZ + (size_t)plane * PIX3 + gp] : 0.f;
    }
    int b = tid / 48, o = tid - b * 48;
    unsigned long long acc[8];
    #pragma unroll
    for (int m = 0; m < 8; m++) acc[m] = 0ull;
    const float* wband = w + (size_t)band * 2304 * PIX3;
    for (int ic = 0; ic < 12; ic++) {
        __syncthreads();
        for (int e = tid; e < 3072; e += 384) {
            int ii = e / 768;
            int rem = e - ii * 768;
            int oo = rem >> 4, px = rem & 15;
            int gp = px0 + px;
            ws[(ii * 48 + oo) * 18 + px] = (gp < PIX3)
                ? wband[((size_t)(ic * 4 + ii) * 48 + oo) * PIX3 + gp] : 0.f;
        }
        __syncthreads();
        #pragma unroll
        for (int i = 0; i < 4; i++) {
            const unsigned long long* tr =
                (const unsigned long long*)(ts + (b * 48 + ic * 4 + i) * 18);
            const unsigned long long* wr =
                (const unsigned long long*)(ws + (i * 48 + o) * 18);
            #pragma unroll
            for (int m = 0; m < 8; m++) acc[m] = ffma2(tr[m], wr[m], acc[m]);
        }
    }
    size_t obase = (size_t)band * B3SZ + (size_t)(b * 48 + o) * PIX3 + px0;
    #pragma unroll
    for (int m = 0; m < 8; m++) {
        float x, y;
        unpack2(acc[m], x, y);
        int gp0 = px0 + 2 * m;
        if (gp0 < PIX3)     b3out[obase + 2 * m]     = x;
        if (gp0 + 1 < PIX3) b3out[obase + 2 * m + 1] = y;
    }
}

// ------------------ pointwise conv + residual add + gelu --------------------
__global__ void pw_kernel(float* __restrict__ h, const float* __restrict__ h2,
                          const float* __restrict__ cw, const float* __restrict__ cb,
                          int do_gelu) {
    __shared__ unsigned long long ws2[2304];
    __shared__ float bs[48];
    int tid = threadIdx.x;
    for (int j = tid; j < 2304; j += 256) {
        int o = j / 48, i = j - o * 48;
        float w = cw[j];
        ws2[i * 48 + o] = pack2(w, w);
    }
    if (tid < 48) bs[tid] = cb[tid];
    __syncthreads();
    int og = tid >> 6;
    int pq = tid & 63;
    int bx = blockIdx.x;
    int bb = bx >> 8;
    int p0 = ((bx & 255) << 8) + (pq << 2);
    size_t base = ((size_t)bb * CC) * HW + p0;
    unsigned long long acc[12][2];
    #pragma unroll
    for (int o = 0; o < 12; o++) {
        float b = bs[og * 12 + o];
        acc[o][0] = pack2(b, b);
        acc[o][1] = acc[o][0];
    }
    for (int i = 0; i < 48; i++) {
        ulonglong2 v = *(const ulonglong2*)(h + base + (size_t)i * HW);
        #pragma unroll
        for (int o = 0; o < 12; o++) {
            unsigned long long w2 = ws2[i * 48 + og * 12 + o];
            acc[o][0] = ffma2(v.x, w2, acc[o][0]);
            acc[o][1] = ffma2(v.y, w2, acc[o][1]);
        }
    }
    __syncthreads();
    #pragma unroll
    for (int o = 0; o < 12; o++) {
        int oc = og * 12 + o;
        float4 r = *(const float4*)(h2 + base + (size_t)oc * HW);
        float a, b, c, d;
        unpack2(acc[o][0], a, b);
        unpack2(acc[o][1], c, d);
        a += r.x; b += r.y; c += r.z; d += r.w;
        if (do_gelu) { a = gelu_f(a); b = gelu_f(b); c = gelu_f(c); d = gelu_f(d); }
        *(float4*)(h + base + (size_t)oc * HW) = make_float4(a, b, c, d);
    }
}

// -------------------------- fused fc1+gelu+fc2 head --------------------------
__global__ void head_kernel(const float* __restrict__ h, const float* __restrict__ w1,
                            const float* __restrict__ b1, const float* __restrict__ w2,
                            const float* __restrict__ b2, float* __restrict__ out) {
    __shared__ unsigned long long w1s[1536];
    __shared__ float b1s[64];
    __shared__ float w2s[64];
    int tid = threadIdx.x;
    const unsigned long long* w1u = (const unsigned long long*)w1;
    for (int j = tid; j < 1536; j += 256) w1s[j] = w1u[j];
    if (tid < 64) { b1s[tid] = b1[tid]; w2s[tid] = w2[tid]; }
    __syncthreads();
    int q = blockIdx.x * 256 + tid;
    if (q >= 8 * 255 * 255) return;
    int c = q % 255;
    int t2 = q / 255;
    int r = t2 % 255;
    int bb = t2 / 255;
    size_t base = ((size_t)bb * CC) * HW + (size_t)r * 256 + c;
    unsigned long long acc[32];
    #pragma unroll
    for (int j = 0; j < 32; j++) acc[j] = pack2(b1s[2 * j], b1s[2 * j + 1]);
    for (int i = 0; i < 48; i++) {
        float v = h[base + (size_t)i * HW];
        unsigned long long vv = pack2(v, v);
        #pragma unroll
        for (int j = 0; j < 32; j++) acc[j] = ffma2(vv, w1s[i * 32 + j], acc[j]);
    }
    float o = b2[0];
    #pragma unroll
    for (int j = 0; j < 32; j++) {
        float a, b;
        unpack2(acc[j], a, b);
        o += gelu_f(a) * w2s[2 * j] + gelu_f(b) * w2s[2 * j + 1];
    }
    out[q] = o;
}

// ---------------------------------- launch ----------------------------------
static inline int grd(long n, int bs) { return (int)((n + bs - 1) / bs); }

// smem sizes (bytes) matching template constexpr math
#define AFB1_SMEM ((7*278 + 2*63*134) * 4)        // 75320
#define AFB2_SMEM ((5*156 + 2*59*72) * 4)         // 37104
#define AFB3_SMEM ((4*94  + 2*93*42) * 4)         // 32752
#define SFB3_SMEM ((4*24*42 + 2*36*42) * 4)       // 28224
#define SFB2_SMEM ((4*23*72 + 2*34*72) * 4)       // 46080
#define SFB1_SMEM ((4*22*134 + 2*32*134) * 4)     // 81472

extern "C" void kernel_launch(void* const* d_in, const int* in_sizes, int n_in,
                              void* d_out, int out_size) {
    const float* x     = (const float*)d_in[0];
    const float* fc0_w = (const float*)d_in[1];
    const float* fc0_b = (const float*)d_in[2];
    const float* wc[4] = { (const float*)d_in[3], (const float*)d_in[4],
                           (const float*)d_in[5], (const float*)d_in[6] };
    const float* cw    = (const float*)d_in[7];
    const float* cb    = (const float*)d_in[8];
    const float* fc1_w = (const float*)d_in[9];
    const float* fc1_b = (const float*)d_in[10];
    const float* fc2_w = (const float*)d_in[11];
    const float* fc2_b = (const float*)d_in[12];
    float* out = (float*)d_out;

    float *h, *h1, *h2, *ll1, *lh1, *hl1, *hh1, *ll2, *lh2, *hl2, *hh2, *b3;
    cudaGetSymbolAddress((void**)&h,   g_h);
    cudaGetSymbolAddress((void**)&h1,  g_h1);
    cudaGetSymbolAddress((void**)&h2,  g_h2);
    cudaGetSymbolAddress((void**)&ll1, g_ll1);
    cudaGetSymbolAddress((void**)&lh1, g_lh1);
    cudaGetSymbolAddress((void**)&hl1, g_hl1);
    cudaGetSymbolAddress((void**)&hh1, g_hh1);
    cudaGetSymbolAddress((void**)&ll2, g_ll2);
    cudaGetSymbolAddress((void**)&lh2, g_lh2);
    cudaGetSymbolAddress((void**)&hl2, g_hl2);
    cudaGetSymbolAddress((void**)&hh2, g_hh2);
    cudaGetSymbolAddress((void**)&b3,  g_b3);

    // raise dynamic smem limits for the two >48KB kernels (idempotent)
    cudaFuncSetAttribute(afb2d<256,256,133,133,10,26,7,256>,
                         cudaFuncAttributeMaxDynamicSharedMemorySize, AFB1_SMEM);
    cudaFuncSetAttribute(sfb2d<133,133,32,512>,
                         cudaFuncAttributeMaxDynamicSharedMemorySize, SFB1_SMEM);

    fc0_kernel<<<grd((long)PP * HW, 256), 256>>>(x, fc0_w, fc0_b, h);

    for (int layer = 0; layer < 4; layer++) {
        // ---------------- forward DWT (3 fused levels) ----------------
        afb2d<256,256,133,133,10,26,7,256><<<dim3(6, PP), 256, AFB1_SMEM>>>(
            h, (long)HW, 256, ll1, lh1, hl1, hh1);
        afb2d<133,133,72,72,11,24,5,256><<<dim3(3, PP), 256, AFB2_SMEM>>>(
            ll1, 133L*133, 133, ll2, lh2, hl2, hh2);
        afb2d<72,72,41,41,10,41,4,256><<<dim3(1, PP), 256, AFB3_SMEM>>>(
            ll2, 72L*72, 72,
            b3 + 0L*B3SZ, b3 + 1L*B3SZ, b3 + 2L*B3SZ, b3 + 3L*B3SZ);

        // ---------------- coarsest-level channel mix ----------------
        mix_kernel<<<dim3(grd(PIX3,16), 4), 384>>>(b3, wc[layer], b3 + 4L*B3SZ);

        // ---------------- inverse DWT (3 fused levels) ----------------
        sfb2d<41,41,36,256><<<dim3(2, PP), 256, SFB3_SMEM>>>(
            b3 + 4L*B3SZ, (long)PIX3, 41,
            b3 + 5L*B3SZ, b3 + 6L*B3SZ, b3 + 7L*B3SZ, (long)PIX3, ll2);
        sfb2d<72,72,34,256><<<dim3(4, PP), 256, SFB2_SMEM>>>(
            ll2, 72L*72, 72, lh2, hl2, hh2, 72L*72, h1);
        sfb2d<133,133,32,512><<<dim3(8, PP), 512, SFB1_SMEM>>>(
            h1, 134L*134, 134, lh1, hl1, hh1, 133L*133, h2);

        // ---------------- pointwise conv + add + gelu ----------------
        pw_kernel<<<2048, 256>>>(h, h2, cw + (size_t)layer * 2304,
                                 cb + (size_t)layer * 48, layer < 3 ? 1 : 0);
    }

    head_kernel<<<grd(8L * 255 * 255, 256), 256>>>(h, fc1_w, fc1_b, fc2_w, fc2_b, out);
}